// round 14
// baseline (speedup 1.0000x reference)
#include <cuda_runtime.h>
#include <cuda_fp16.h>
#include <math.h>
#include <stdint.h>

#define B_  4
#define L_  2048
#define D_  1024
#define H_  16
#define DH  64
#define M_  (B_*L_)        /* 8192 */
#define NF_ (D_/2)         /* 512 */
#define NEG 1e7f

// -------------------- scratch --------------------
__device__ __half g_qpe[M_*D_];
__device__ __half g_kpe[M_*D_];
__device__ __half g_vr [M_*D_];
__device__ __half g_Qh[M_*D_];    // [B,H,L,DH]  (Q pre-scaled by 0.125*log2e)
__device__ __half g_Kh[M_*D_];
__device__ __half g_Vh[M_*D_];
__device__ __half g_attn[M_*D_];  // [B,L,D]
__device__ __half g_Wt[4*D_*D_];  // transposed weights [N][K]

// -------------------- helpers --------------------
__device__ __forceinline__ void mma16(float* c, const unsigned* a, const unsigned* b){
    asm volatile("mma.sync.aligned.m16n8k16.row.col.f32.f16.f16.f32 "
        "{%0,%1,%2,%3}, {%4,%5,%6,%7}, {%8,%9}, {%0,%1,%2,%3};"
        : "+f"(c[0]),"+f"(c[1]),"+f"(c[2]),"+f"(c[3])
        : "r"(a[0]),"r"(a[1]),"r"(a[2]),"r"(a[3]),"r"(b[0]),"r"(b[1]));
}
__device__ __forceinline__ void ldsm_x4(unsigned* r, uint32_t a){
    asm volatile("ldmatrix.sync.aligned.m8n8.x4.shared.b16 {%0,%1,%2,%3}, [%4];"
        : "=r"(r[0]),"=r"(r[1]),"=r"(r[2]),"=r"(r[3]) : "r"(a));
}
__device__ __forceinline__ void ldsm_x4t(unsigned* r, uint32_t a){
    asm volatile("ldmatrix.sync.aligned.m8n8.x4.trans.shared.b16 {%0,%1,%2,%3}, [%4];"
        : "=r"(r[0]),"=r"(r[1]),"=r"(r[2]),"=r"(r[3]) : "r"(a));
}
__device__ __forceinline__ uint32_t smem_u32(const void* p){
    uint32_t a; asm("{ .reg .u64 t; cvta.to.shared.u64 t, %1; cvt.u32.u64 %0, t; }"
                    : "=r"(a) : "l"(p)); return a;
}
__device__ __forceinline__ void cp16(uint32_t dst, const void* src){
    asm volatile("cp.async.cg.shared.global [%0], [%1], 16;" :: "r"(dst), "l"(src));
}
#define CP_COMMIT() asm volatile("cp.async.commit_group;" ::: "memory")
#define CP_WAIT1()  asm volatile("cp.async.wait_group 1;" ::: "memory")
#define CP_WAIT0()  asm volatile("cp.async.wait_group 0;" ::: "memory")
__device__ __forceinline__ float fexp2(float x){
    float y; asm("ex2.approx.ftz.f32 %0, %1;" : "=f"(y) : "f"(x)); return y;
}

// -------------------- PE add (fp32 math -> half; R11 version) --------------------
__global__ void pe_add_kernel(const float* __restrict__ q, const float* __restrict__ k,
                              const float* __restrict__ v) {
    int i = blockIdx.x * blockDim.x + threadIdx.x;
    if (i >= M_ * NF_) return;
    int row = i / NF_;
    int f   = i - row * NF_;
    int l   = row & (L_ - 1);
    const float kC = 9.210340371976184f / 512.0f;
    float ang = (float)l * expf(-(float)f * kC);
    float s, c;
    sincosf(ang, &s, &c);
    int base = row * D_ + 2 * f;
    *(half2*)&g_qpe[base] = __floats2half2_rn(q[base] + s, q[base+1] + c);
    *(half2*)&g_kpe[base] = __floats2half2_rn(k[base] + s, k[base+1] + c);
    *(half2*)&g_vr[base]  = __floats2half2_rn(v[base],     v[base+1]);
}

// -------------------- weight transpose -> half [N][K] --------------------
__global__ void transpose_w4(const float* __restrict__ W0, const float* __restrict__ W1,
                             const float* __restrict__ W2, const float* __restrict__ W3){
    __shared__ float t[32][33];
    const float* W = (blockIdx.z==0)?W0:(blockIdx.z==1)?W1:(blockIdx.z==2)?W2:W3;
    __half* O = g_Wt + (size_t)blockIdx.z * D_ * D_;
    int x0 = blockIdx.x*32, y0 = blockIdx.y*32;
    int tx = threadIdx.x, ty0 = threadIdx.y;   // (32, 8)
#pragma unroll
    for (int i=0;i<4;i++){ int ty=ty0+i*8; t[ty][tx] = W[(size_t)(y0+ty)*D_ + x0+tx]; }
    __syncthreads();
#pragma unroll
    for (int i=0;i<2;i++){
        int kk = ty0 + i*8;
        half2 h = __floats2half2_rn(t[2*kk][tx], t[2*kk+1][tx]);
        *(half2*)&O[(size_t)(x0+tx)*D_ + y0 + 2*kk] = h;
    }
}

// -------------------- fp16 GEMM: BK=64, 3-stage cp.async, optional QKV fusion -----
#define GS 32768
#define G_SMEM (3*GS)

template<int QKV>
__global__ void __launch_bounds__(128, 2)
gemm_h5(const __half* __restrict__ A0, const __half* __restrict__ A1,
        const __half* __restrict__ A2, const __half* __restrict__ WtBase,
        const float* __restrict__ b0, const float* __restrict__ b1,
        const float* __restrict__ b2,
        void* O0, void* O1, void* O2, float qs){
    extern __shared__ __align__(128) char smem[];
    uint32_t sb = smem_u32(smem);
    int z = QKV ? blockIdx.z : 0;
    const __half* A    = (z==0)?A0:(z==1)?A1:A2;
    const __half* Wt   = WtBase + (size_t)(QKV ? z : 3) * D_ * D_;
    const float*  bias = (z==0)?b0:(z==1)?b1:b2;
    void* Cv           = (z==0)?O0:(z==1)?O1:O2;
    float oscale       = (QKV && z==0) ? qs : 1.f;

    int tid=threadIdx.x, lane=tid&31;
    int warp=tid>>5, wm=warp>>1, wn=warp&1;
    int bm=blockIdx.y*128, bn=blockIdx.x*128;

    const __half* Ab = A  + (size_t)bm * D_;
    const __half* Bb = Wt + (size_t)bn * D_;

    float acc[4][8][4];
#pragma unroll
    for(int i=0;i<4;i++)
#pragma unroll
      for(int j=0;j<8;j++)
#pragma unroll
        for(int r=0;r<4;r++) acc[i][j][r]=0.f;

    int prr = tid>>3, prc = tid&7;
    uint32_t stoff[8]; int prow[8];
#pragma unroll
    for(int it=0;it<8;it++){
        int r = prr + 16*it;
        prow[it] = r;
        stoff[it] = r*128 + 16*(prc ^ (r&7));
    }

    int l7=lane&7, g8=(lane>>3)&1, g16=lane>>4;
    uint32_t aRow[4]; int aSwz[4];
#pragma unroll
    for(int mt=0;mt<4;mt++){
        int r = wm*64 + mt*16 + l7 + g8*8;
        aRow[mt] = r*128; aSwz[mt] = r&7;
    }
    uint32_t bRow[4]; int bSwz[4];
#pragma unroll
    for(int ntp=0;ntp<4;ntp++){
        int n = wn*64 + ntp*16 + l7 + g16*8;
        bRow[ntp] = 16384u + n*128; bSwz[ntp] = n&7;
    }

    auto issue=[&](int ch){
        int s = ch % 3;
        uint32_t da = sb + s*GS;
#pragma unroll
        for(int it=0;it<8;it++){
            cp16(da + stoff[it],          Ab + (size_t)prow[it]*D_ + ch*64 + prc*8);
            cp16(da + 16384 + stoff[it],  Bb + (size_t)prow[it]*D_ + ch*64 + prc*8);
        }
        CP_COMMIT();
    };

    issue(0); issue(1);

    for(int ch=0; ch<16; ch++){
        if(ch<15) CP_WAIT1(); else CP_WAIT0();
        __syncthreads();
        if(ch+2<16) issue(ch+2);
        uint32_t so = sb + (ch%3)*GS;
#pragma unroll
        for(int ks=0;ks<4;ks++){
            unsigned bf[4][4];
#pragma unroll
            for(int ntp=0;ntp<4;ntp++)
                ldsm_x4(bf[ntp], so + bRow[ntp] + 16*((2*ks+g8)^bSwz[ntp]));
#pragma unroll
            for(int mt=0;mt<4;mt++){
                unsigned af[4];
                ldsm_x4(af, so + aRow[mt] + 16*((2*ks+g16)^aSwz[mt]));
#pragma unroll
                for(int ntp=0;ntp<4;ntp++){
                    mma16(acc[mt][2*ntp+0], af, &bf[ntp][0]);
                    mma16(acc[mt][2*ntp+1], af, &bf[ntp][2]);
                }
            }
        }
    }

#pragma unroll
    for(int mt=0;mt<4;mt++){
        int r0 = bm + wm*64 + mt*16 + (lane>>2);
#pragma unroll
        for(int hf=0;hf<2;hf++){
            int m = r0 + hf*8;
            int bidx = m>>11, l = m&(L_-1);
#pragma unroll
            for(int nt=0;nt<8;nt++){
                int n = bn + wn*64 + nt*8 + 2*(lane&3);
                float2 bb = *(const float2*)&bias[n];
                float v0 = (acc[mt][nt][hf*2+0] + bb.x) * oscale;
                float v1 = (acc[mt][nt][hf*2+1] + bb.y) * oscale;
                if(QKV){
                    int h=n>>6, dd=n&63;
                    *(half2*)&((__half*)Cv)[(size_t)((bidx*H_+h)*L_+l)*DH + dd] =
                        __floats2half2_rn(v0, v1);
                } else {
                    float2 ov = make_float2(v0, v1);
                    *(float2*)&((float*)Cv)[(size_t)m*D_ + n] = ov;
                }
            }
        }
    }
}

// -------------------- fp16 flash attention: R11 + causal tile skipping -----------
// Scores in log2 units (Q pre-scaled by 0.125*log2e). 128-row Q tiles,
// K/V double buffers of 128 keys; softmax in two 64-key halves.
// Diagonal tiles: 16x16 units fully above the diagonal are skipped outright
// (their P is exactly 0) — S-MMAs, K/V ldsm, and PV-MMAs elided, bit-identical.
#define AQ 0                 /* 16KB */
#define AK 16384             /* 2 x 16KB */
#define AV 49152             /* 2 x 16KB */
#define APAD 81920           /* 128 floats */
#define AFLAG (APAD + 512)
#define ATTN_SMEM (AFLAG + 16)

__global__ void __launch_bounds__(256, 2)
attn_h(const unsigned char* __restrict__ pad, __half* __restrict__ outp){
    extern __shared__ __align__(128) char smem[];
    uint32_t sb = smem_u32(smem);
    float* spad = (float*)(smem + APAD);
    int* flagp  = (int*)(smem + AFLAG);

    int tid=threadIdx.x, lane=tid&31, warp=tid>>5;
    int qt = (int)(gridDim.x - 1) - (int)blockIdx.x;   // long blocks first
    int bh=blockIdx.y;
    int b=bh>>4, h=bh&15;
    const __half* Q = g_Qh + (size_t)bh*L_*DH;
    const __half* K = g_Kh + (size_t)bh*L_*DH;
    const __half* V = g_Vh + (size_t)bh*L_*DH;

#pragma unroll
    for(int t=0;t<4;t++){
        int idx=t*256+tid;
        int r=idx>>3, c=idx&7;
        cp16(sb + AQ + r*128 + 16*(c ^ (r&7)),
             Q + (size_t)(qt*128+r)*DH + c*8);
    }
    CP_COMMIT();

    auto issueKV=[&](int kt2){
        uint32_t buf = (kt2&1)*16384u;
#pragma unroll
        for(int t=0;t<4;t++){
            int idx=t*256+tid;
            int r=idx>>3, c=idx&7;
            uint32_t off = r*128 + 16*(c ^ (r&7));
            cp16(sb + AK + buf + off, K + (size_t)(kt2*128+r)*DH + c*8);
            cp16(sb + AV + buf + off, V + (size_t)(kt2*128+r)*DH + c*8);
        }
        CP_COMMIT();
    };
    issueKV(0);

    int nkt2 = qt+1;

    // ---- block-level padding flag over the whole key range (once) ----
    if(tid==0) *flagp = 0;
    __syncthreads();
    {
        int npad = nkt2*128;
        unsigned a=0;
        for(int i=tid*4; i<npad; i+=1024)
            a |= *(const unsigned*)(pad + b*L_ + i);
        a = __reduce_or_sync(0xffffffffu, a);
        if((tid&31)==0 && a) atomicOr(flagp, 1);
    }
    __syncthreads();
    bool haspad = (*flagp) != 0;

    int l7=lane&7, g8=(lane>>3)&1, g16=lane>>4;
    int rqa = warp*16 + l7 + g8*8;
    uint32_t qOff = AQ + rqa*128;  int qSwz = rqa&7;
    uint32_t kOff[4]; int kSwz[4];
#pragma unroll
    for(int ntp=0;ntp<4;ntp++){
        int n = ntp*16 + l7 + g16*8;
        kOff[ntp] = AK + n*128; kSwz[ntp] = n&7;
    }
    int rq0 = lane>>2;
    int vRow[4];
#pragma unroll
    for(int ks=0;ks<4;ks++) vRow[ks] = ks*16 + l7 + g8*8;

    const unsigned onesf[2] = {0x3C003C00u, 0x3C003C00u};  // B = ones (fp16 1.0)

    float m_[2]={-1e30f,-1e30f}, l_[2]={0.f,0.f};
    float o[8][4];
#pragma unroll
    for(int i=0;i<8;i++){o[i][0]=0.f;o[i][1]=0.f;o[i][2]=0.f;o[i][3]=0.f;}
    int r0g = qt*128 + warp*16 + rq0;
    int r1g = r0g + 8;

    for(int kt2=0;kt2<nkt2;kt2++){
        __syncthreads();                 // all warps done with buffer (kt2+1)&1
        if(kt2+1<nkt2){ issueKV(kt2+1); CP_WAIT1(); }
        else          { CP_WAIT0(); }
        if(haspad && warp==1){
#pragma unroll
            for(int j=0;j<4;j++){
                int idx = lane*4 + j;
                spad[idx] = pad[b*L_ + kt2*128 + idx] ? NEG : 0.f;
            }
        }
        __syncthreads();                 // KV(kt2) + spad visible
        bool diag = (kt2 == qt);
        bool fast = diag && !haspad;     // causal tile-skip path

#pragma unroll
        for(int hk=0;hk<2;hk++){
            uint32_t kvb = (kt2&1)*16384u + hk*8192u;
            const float* sp = spad + hk*64;

            // ---- S = Q K^T (log2 units); skip fully-masked units in fast path ----
            float s[8][4];
#pragma unroll
            for(int i=0;i<8;i++){s[i][0]=0.f;s[i][1]=0.f;s[i][2]=0.f;s[i][3]=0.f;}
#pragma unroll
            for(int ks=0;ks<4;ks++){
                unsigned af[4];
                ldsm_x4(af, sb + qOff + 16*((2*ks + g16) ^ qSwz));
#pragma unroll
                for(int ntp=0;ntp<4;ntp++){
                    if(fast && (hk*4+ntp > warp)) continue;
                    unsigned bf[4];
                    ldsm_x4(bf, sb + kOff[ntp] + kvb + 16*((2*ks + g8) ^ kSwz[ntp]));
                    mma16(s[2*ntp+0], af, &bf[0]);
                    mma16(s[2*ntp+1], af, &bf[2]);
                }
            }

            // ---- mask + row max ----
            float rmax0=-1e30f, rmax1=-1e30f;
            if(diag){
                int cbase = kt2*128 + hk*64;
                if(haspad){
#pragma unroll
                    for(int nt=0;nt<8;nt++){
                        int cl = nt*8 + 2*(lane&3);
                        int c0 = cbase + cl, c1 = c0+1;
                        float ms0=sp[cl], ms1=sp[cl+1];
                        float v0=s[nt][0] - ms0; if(c0>r0g) v0-=NEG;
                        float v1=s[nt][1] - ms1; if(c1>r0g) v1-=NEG;
                        float v2=s[nt][2] - ms0; if(c0>r1g) v2-=NEG;
                        float v3=s[nt][3] - ms1; if(c1>r1g) v3-=NEG;
                        s[nt][0]=v0; s[nt][1]=v1; s[nt][2]=v2; s[nt][3]=v3;
                        rmax0=fmaxf(rmax0,fmaxf(v0,v1));
                        rmax1=fmaxf(rmax1,fmaxf(v2,v3));
                    }
                } else {
#pragma unroll
                    for(int nt=0;nt<8;nt++){
                        int u = hk*4 + (nt>>1);
                        if(u > warp) continue;        // fully masked: excluded
                        if(u == warp){                // diagonal unit: per-element
                            int cl = nt*8 + 2*(lane&3);
                            int c0 = cbase + cl, c1 = c0+1;
                            float v0=s[nt][0]; if(c0>r0g) v0-=NEG;
                            float v1=s[nt][1]; if(c1>r0g) v1-=NEG;
                            float v2=s[nt][2]; if(c0>r1g) v2-=NEG;
                            float v3=s[nt][3]; if(c1>r1g) v3-=NEG;
                            s[nt][0]=v0; s[nt][1]=v1; s[nt][2]=v2; s[nt][3]=v3;
                            rmax0=fmaxf(rmax0,fmaxf(v0,v1));
                            rmax1=fmaxf(rmax1,fmaxf(v2,v3));
                        } else {                       // fully unmasked
                            rmax0=fmaxf(rmax0,fmaxf(s[nt][0],s[nt][1]));
                            rmax1=fmaxf(rmax1,fmaxf(s[nt][2],s[nt][3]));
                        }
                    }
                }
            } else {
                if(haspad){
#pragma unroll
                    for(int nt=0;nt<8;nt++){
                        int cl = nt*8 + 2*(lane&3);
                        float ms0=sp[cl], ms1=sp[cl+1];
                        float v0=s[nt][0] - ms0;
                        float v1=s[nt][1] - ms1;
                        float v2=s[nt][2] - ms0;
                        float v3=s[nt][3] - ms1;
                        s[nt][0]=v0; s[nt][1]=v1; s[nt][2]=v2; s[nt][3]=v3;
                        rmax0=fmaxf(rmax0,fmaxf(v0,v1));
                        rmax1=fmaxf(rmax1,fmaxf(v2,v3));
                    }
                } else {
#pragma unroll
                    for(int nt=0;nt<8;nt++){
                        rmax0=fmaxf(rmax0,fmaxf(s[nt][0],s[nt][1]));
                        rmax1=fmaxf(rmax1,fmaxf(s[nt][2],s[nt][3]));
                    }
                }
            }

            // ---- packed half2 max reduce (2 shfl) ----
            rmax0 = fmaxf(rmax0, -60000.f);
            rmax1 = fmaxf(rmax1, -60000.f);
            half2 mh = __floats2half2_rn(rmax0, rmax1);
            unsigned mu = *(unsigned*)&mh;
            unsigned ms1_ = __shfl_xor_sync(0xffffffffu, mu, 1);
            mh = __hmax2(mh, *(half2*)&ms1_);
            mu = *(unsigned*)&mh;
            unsigned ms2_ = __shfl_xor_sync(0xffffffffu, mu, 2);
            mh = __hmax2(mh, *(half2*)&ms2_);
            float2 rmf = __half22float2(mh);

            float mn0=fmaxf(m_[0],rmf.x), mn1=fmaxf(m_[1],rmf.y);
            float corr0=fexp2(m_[0]-mn0), corr1=fexp2(m_[1]-mn1);
            m_[0]=mn0; m_[1]=mn1;

            // ---- exp2 in f16x2 -> P stays in registers ----
            unsigned eh01[8], eh23[8];
            if(fast){
#pragma unroll
                for(int nt=0;nt<8;nt++){
                    int u = hk*4 + (nt>>1);
                    if(u > warp){ eh01[nt]=0u; eh23[nt]=0u; }
                    else {
                        half2 e01 = h2exp2(__floats2half2_rn(s[nt][0]-mn0, s[nt][1]-mn0));
                        half2 e23 = h2exp2(__floats2half2_rn(s[nt][2]-mn1, s[nt][3]-mn1));
                        eh01[nt] = *(unsigned*)&e01;
                        eh23[nt] = *(unsigned*)&e23;
                    }
                }
            } else {
#pragma unroll
                for(int nt=0;nt<8;nt++){
                    half2 e01 = h2exp2(__floats2half2_rn(s[nt][0]-mn0, s[nt][1]-mn0));
                    half2 e23 = h2exp2(__floats2half2_rn(s[nt][2]-mn1, s[nt][3]-mn1));
                    eh01[nt] = *(unsigned*)&e01;
                    eh23[nt] = *(unsigned*)&e23;
                }
            }
#pragma unroll
            for(int nt=0;nt<8;nt++){
                o[nt][0]*=corr0; o[nt][1]*=corr0;
                o[nt][2]*=corr1; o[nt][3]*=corr1;
            }

            // ---- O += P V ; row sums via P*ones MMA ; skip zero-P key blocks ----
            float lsum[4]={0.f,0.f,0.f,0.f};
#pragma unroll
            for(int ks=0;ks<4;ks++){
                if(fast && (hk*4+ks > warp)) continue;
                unsigned pf[4] = {eh01[2*ks], eh23[2*ks], eh01[2*ks+1], eh23[2*ks+1]};
                mma16(lsum, pf, onesf);
                uint32_t vbase = AV + kvb + vRow[ks]*128;
                int vSwz = vRow[ks]&7;
#pragma unroll
                for(int ntp=0;ntp<4;ntp++){
                    unsigned bf[4];
                    ldsm_x4t(bf, sb + vbase + 16*((2*ntp + g16) ^ vSwz));
                    mma16(o[2*ntp+0], pf, &bf[0]);
                    mma16(o[2*ntp+1], pf, &bf[2]);
                }
            }
            l_[0]=l_[0]*corr0+lsum[0];
            l_[1]=l_[1]*corr1+lsum[2];
        }
    }

    // ---- normalize + write half [B,L,D] ----
    float inv0=1.f/l_[0], inv1=1.f/l_[1];
#pragma unroll
    for(int nt=0;nt<8;nt++){
        int dd = nt*8 + 2*(lane&3);
        *(half2*)&outp[(size_t)(b*L_+r0g)*D_ + h*DH + dd] =
            __floats2half2_rn(o[nt][0]*inv0, o[nt][1]*inv0);
        *(half2*)&outp[(size_t)(b*L_+r1g)*D_ + h*DH + dd] =
            __floats2half2_rn(o[nt][2]*inv1, o[nt][3]*inv1);
    }
}

// -------------------- launch --------------------
extern "C" void kernel_launch(void* const* d_in, const int* in_sizes, int n_in,
                              void* d_out, int out_size) {
    const float* q  = (const float*)d_in[0];
    const float* k  = (const float*)d_in[1];
    const float* v  = (const float*)d_in[2];
    const unsigned char* pad = (const unsigned char*)d_in[3];
    const float* Wq = (const float*)d_in[4];
    const float* bq = (const float*)d_in[5];
    const float* Wk = (const float*)d_in[6];
    const float* bk = (const float*)d_in[7];
    const float* Wv = (const float*)d_in[8];
    const float* bv = (const float*)d_in[9];
    const float* Wo = (const float*)d_in[10];
    const float* bo = (const float*)d_in[11];
    float* out = (float*)d_out;

    __half *p_qpe, *p_kpe, *p_vr, *p_Qh, *p_Kh, *p_Vh, *p_attn, *p_Wt;
    cudaGetSymbolAddress((void**)&p_qpe,  g_qpe);
    cudaGetSymbolAddress((void**)&p_kpe,  g_kpe);
    cudaGetSymbolAddress((void**)&p_vr,   g_vr);
    cudaGetSymbolAddress((void**)&p_Qh,   g_Qh);
    cudaGetSymbolAddress((void**)&p_Kh,   g_Kh);
    cudaGetSymbolAddress((void**)&p_Vh,   g_Vh);
    cudaGetSymbolAddress((void**)&p_attn, g_attn);
    cudaGetSymbolAddress((void**)&p_Wt,   g_Wt);

    cudaFuncSetAttribute(attn_h, cudaFuncAttributeMaxDynamicSharedMemorySize, ATTN_SMEM);
    cudaFuncSetAttribute(gemm_h5<0>, cudaFuncAttributeMaxDynamicSharedMemorySize, G_SMEM);
    cudaFuncSetAttribute(gemm_h5<1>, cudaFuncAttributeMaxDynamicSharedMemorySize, G_SMEM);

    // 0) weight transposes -> half [N][K]
    transpose_w4<<<dim3(32,32,4), dim3(32,8)>>>(Wq, Wk, Wv, Wo);

    // 1) positional encodings -> half
    int pe_threads = M_ * NF_;
    pe_add_kernel<<<(pe_threads + 255) / 256, 256>>>(q, k, v);

    // 2) fused QKV projections -> head layout (half); Q pre-scaled by 0.125*log2e
    gemm_h5<1><<<dim3(8, 64, 3), 128, G_SMEM>>>(
        p_qpe, p_kpe, p_vr, p_Wt, bq, bk, bv,
        (void*)p_Qh, (void*)p_Kh, (void*)p_Vh, 0.18033688f);

    // 3) fused causal flash attention (R11 + diag tile skipping)
    attn_h<<<dim3(L_ / 128, B_ * H_), 256, ATTN_SMEM>>>(pad, p_attn);

    // 4) output projection -> fp32 d_out
    gemm_h5<0><<<dim3(8, 64, 1), 128, G_SMEM>>>(
        p_attn, nullptr, nullptr, p_Wt, bo, nullptr, nullptr,
        (void*)out, nullptr, nullptr, 1.0f);
}

// round 15
// speedup vs baseline: 1.0186x; 1.0186x over previous
#include <cuda_runtime.h>
#include <cuda_fp16.h>
#include <math.h>
#include <stdint.h>

#define B_  4
#define L_  2048
#define D_  1024
#define H_  16
#define DH  64
#define M_  (B_*L_)        /* 8192 */
#define NF_ (D_/2)         /* 512 */
#define NEG 1e7f

// -------------------- scratch --------------------
__device__ __half g_qpe[M_*D_];
__device__ __half g_kpe[M_*D_];
__device__ __half g_vr [M_*D_];
__device__ __half g_Qh[M_*D_];    // [B,H,L,DH]  (Q pre-scaled by 0.125*log2e)
__device__ __half g_Kh[M_*D_];
__device__ __half g_Vh[M_*D_];
__device__ __half g_attn[M_*D_];  // [B,L,D]
__device__ __half g_Wt[4*D_*D_];  // transposed weights [N][K]

// -------------------- helpers --------------------
__device__ __forceinline__ void mma16(float* c, const unsigned* a, const unsigned* b){
    asm volatile("mma.sync.aligned.m16n8k16.row.col.f32.f16.f16.f32 "
        "{%0,%1,%2,%3}, {%4,%5,%6,%7}, {%8,%9}, {%0,%1,%2,%3};"
        : "+f"(c[0]),"+f"(c[1]),"+f"(c[2]),"+f"(c[3])
        : "r"(a[0]),"r"(a[1]),"r"(a[2]),"r"(a[3]),"r"(b[0]),"r"(b[1]));
}
__device__ __forceinline__ void ldsm_x4(unsigned* r, uint32_t a){
    asm volatile("ldmatrix.sync.aligned.m8n8.x4.shared.b16 {%0,%1,%2,%3}, [%4];"
        : "=r"(r[0]),"=r"(r[1]),"=r"(r[2]),"=r"(r[3]) : "r"(a));
}
__device__ __forceinline__ void ldsm_x4t(unsigned* r, uint32_t a){
    asm volatile("ldmatrix.sync.aligned.m8n8.x4.trans.shared.b16 {%0,%1,%2,%3}, [%4];"
        : "=r"(r[0]),"=r"(r[1]),"=r"(r[2]),"=r"(r[3]) : "r"(a));
}
__device__ __forceinline__ uint32_t smem_u32(const void* p){
    uint32_t a; asm("{ .reg .u64 t; cvta.to.shared.u64 t, %1; cvt.u32.u64 %0, t; }"
                    : "=r"(a) : "l"(p)); return a;
}
__device__ __forceinline__ void cp16(uint32_t dst, const void* src){
    asm volatile("cp.async.cg.shared.global [%0], [%1], 16;" :: "r"(dst), "l"(src));
}
#define CP_COMMIT() asm volatile("cp.async.commit_group;" ::: "memory")
#define CP_WAIT1()  asm volatile("cp.async.wait_group 1;" ::: "memory")
#define CP_WAIT0()  asm volatile("cp.async.wait_group 0;" ::: "memory")
__device__ __forceinline__ float fexp2(float x){
    float y; asm("ex2.approx.ftz.f32 %0, %1;" : "=f"(y) : "f"(x)); return y;
}

// -------------------- PE add (fp32 math -> half) --------------------
__global__ void pe_add_kernel(const float* __restrict__ q, const float* __restrict__ k,
                              const float* __restrict__ v) {
    int i = blockIdx.x * blockDim.x + threadIdx.x;
    if (i >= M_ * NF_) return;
    int row = i / NF_;
    int f   = i - row * NF_;
    int l   = row & (L_ - 1);
    const float kC = 9.210340371976184f / 512.0f;
    float ang = (float)l * expf(-(float)f * kC);
    float s, c;
    sincosf(ang, &s, &c);
    int base = row * D_ + 2 * f;
    *(half2*)&g_qpe[base] = __floats2half2_rn(q[base] + s, q[base+1] + c);
    *(half2*)&g_kpe[base] = __floats2half2_rn(k[base] + s, k[base+1] + c);
    *(half2*)&g_vr[base]  = __floats2half2_rn(v[base],     v[base+1]);
}

// -------------------- weight transpose -> half [N][K] --------------------
__global__ void transpose_w4(const float* __restrict__ W0, const float* __restrict__ W1,
                             const float* __restrict__ W2, const float* __restrict__ W3){
    __shared__ float t[32][33];
    const float* W = (blockIdx.z==0)?W0:(blockIdx.z==1)?W1:(blockIdx.z==2)?W2:W3;
    __half* O = g_Wt + (size_t)blockIdx.z * D_ * D_;
    int x0 = blockIdx.x*32, y0 = blockIdx.y*32;
    int tx = threadIdx.x, ty0 = threadIdx.y;   // (32, 8)
#pragma unroll
    for (int i=0;i<4;i++){ int ty=ty0+i*8; t[ty][tx] = W[(size_t)(y0+ty)*D_ + x0+tx]; }
    __syncthreads();
#pragma unroll
    for (int i=0;i<2;i++){
        int kk = ty0 + i*8;
        half2 h = __floats2half2_rn(t[2*kk][tx], t[2*kk+1][tx]);
        *(half2*)&O[(size_t)(x0+tx)*D_ + y0 + 2*kk] = h;
    }
}

// -------------------- fp16 GEMM: BK=64, 3-stage cp.async, optional QKV fusion -----
#define GS 32768
#define G_SMEM (3*GS)

template<int QKV>
__global__ void __launch_bounds__(128, 2)
gemm_h5(const __half* __restrict__ A0, const __half* __restrict__ A1,
        const __half* __restrict__ A2, const __half* __restrict__ WtBase,
        const float* __restrict__ b0, const float* __restrict__ b1,
        const float* __restrict__ b2,
        void* O0, void* O1, void* O2, float qs){
    extern __shared__ __align__(128) char smem[];
    uint32_t sb = smem_u32(smem);
    int z = QKV ? blockIdx.z : 0;
    const __half* A    = (z==0)?A0:(z==1)?A1:A2;
    const __half* Wt   = WtBase + (size_t)(QKV ? z : 3) * D_ * D_;
    const float*  bias = (z==0)?b0:(z==1)?b1:b2;
    void* Cv           = (z==0)?O0:(z==1)?O1:O2;
    float oscale       = (QKV && z==0) ? qs : 1.f;

    int tid=threadIdx.x, lane=tid&31;
    int warp=tid>>5, wm=warp>>1, wn=warp&1;
    int bm=blockIdx.y*128, bn=blockIdx.x*128;

    const __half* Ab = A  + (size_t)bm * D_;
    const __half* Bb = Wt + (size_t)bn * D_;

    float acc[4][8][4];
#pragma unroll
    for(int i=0;i<4;i++)
#pragma unroll
      for(int j=0;j<8;j++)
#pragma unroll
        for(int r=0;r<4;r++) acc[i][j][r]=0.f;

    int prr = tid>>3, prc = tid&7;
    uint32_t stoff[8]; int prow[8];
#pragma unroll
    for(int it=0;it<8;it++){
        int r = prr + 16*it;
        prow[it] = r;
        stoff[it] = r*128 + 16*(prc ^ (r&7));
    }

    int l7=lane&7, g8=(lane>>3)&1, g16=lane>>4;
    uint32_t aRow[4]; int aSwz[4];
#pragma unroll
    for(int mt=0;mt<4;mt++){
        int r = wm*64 + mt*16 + l7 + g8*8;
        aRow[mt] = r*128; aSwz[mt] = r&7;
    }
    uint32_t bRow[4]; int bSwz[4];
#pragma unroll
    for(int ntp=0;ntp<4;ntp++){
        int n = wn*64 + ntp*16 + l7 + g16*8;
        bRow[ntp] = 16384u + n*128; bSwz[ntp] = n&7;
    }

    auto issue=[&](int ch){
        int s = ch % 3;
        uint32_t da = sb + s*GS;
#pragma unroll
        for(int it=0;it<8;it++){
            cp16(da + stoff[it],          Ab + (size_t)prow[it]*D_ + ch*64 + prc*8);
            cp16(da + 16384 + stoff[it],  Bb + (size_t)prow[it]*D_ + ch*64 + prc*8);
        }
        CP_COMMIT();
    };

    issue(0); issue(1);

    for(int ch=0; ch<16; ch++){
        if(ch<15) CP_WAIT1(); else CP_WAIT0();
        __syncthreads();
        if(ch+2<16) issue(ch+2);
        uint32_t so = sb + (ch%3)*GS;
#pragma unroll
        for(int ks=0;ks<4;ks++){
            unsigned bf[4][4];
#pragma unroll
            for(int ntp=0;ntp<4;ntp++)
                ldsm_x4(bf[ntp], so + bRow[ntp] + 16*((2*ks+g8)^bSwz[ntp]));
#pragma unroll
            for(int mt=0;mt<4;mt++){
                unsigned af[4];
                ldsm_x4(af, so + aRow[mt] + 16*((2*ks+g16)^aSwz[mt]));
#pragma unroll
                for(int ntp=0;ntp<4;ntp++){
                    mma16(acc[mt][2*ntp+0], af, &bf[ntp][0]);
                    mma16(acc[mt][2*ntp+1], af, &bf[ntp][2]);
                }
            }
        }
    }

#pragma unroll
    for(int mt=0;mt<4;mt++){
        int r0 = bm + wm*64 + mt*16 + (lane>>2);
#pragma unroll
        for(int hf=0;hf<2;hf++){
            int m = r0 + hf*8;
            int bidx = m>>11, l = m&(L_-1);
#pragma unroll
            for(int nt=0;nt<8;nt++){
                int n = bn + wn*64 + nt*8 + 2*(lane&3);
                float2 bb = *(const float2*)&bias[n];
                float v0 = (acc[mt][nt][hf*2+0] + bb.x) * oscale;
                float v1 = (acc[mt][nt][hf*2+1] + bb.y) * oscale;
                if(QKV){
                    int h=n>>6, dd=n&63;
                    *(half2*)&((__half*)Cv)[(size_t)((bidx*H_+h)*L_+l)*DH + dd] =
                        __floats2half2_rn(v0, v1);
                } else {
                    float2 ov = make_float2(v0, v1);
                    *(float2*)&((float*)Cv)[(size_t)m*D_ + n] = ov;
                }
            }
        }
    }
}

// -------------------- fp16 flash attention: single 128-key softmax pass ----------
// Scores in log2 units (Q pre-scaled by 0.125*log2e). 128-row Q tiles,
// K/V double buffers of 128 keys; ONE softmax (max/corr/rescale) per 128 keys.
// P register-resident; row sums via P*ones MMA. Padding flag hoisted per-CTA.
#define AQ 0                 /* 16KB */
#define AK 16384             /* 2 x 16KB */
#define AV 49152             /* 2 x 16KB */
#define APAD 81920           /* 128 floats */
#define AFLAG (APAD + 512)
#define ATTN_SMEM (AFLAG + 16)

__global__ void __launch_bounds__(256, 2)
attn_h(const unsigned char* __restrict__ pad, __half* __restrict__ outp){
    extern __shared__ __align__(128) char smem[];
    uint32_t sb = smem_u32(smem);
    float* spad = (float*)(smem + APAD);
    int* flagp  = (int*)(smem + AFLAG);

    int tid=threadIdx.x, lane=tid&31, warp=tid>>5;
    int qt = (int)(gridDim.x - 1) - (int)blockIdx.x;   // long blocks first
    int bh=blockIdx.y;
    int b=bh>>4, h=bh&15;
    const __half* Q = g_Qh + (size_t)bh*L_*DH;
    const __half* K = g_Kh + (size_t)bh*L_*DH;
    const __half* V = g_Vh + (size_t)bh*L_*DH;

#pragma unroll
    for(int t=0;t<4;t++){
        int idx=t*256+tid;
        int r=idx>>3, c=idx&7;
        cp16(sb + AQ + r*128 + 16*(c ^ (r&7)),
             Q + (size_t)(qt*128+r)*DH + c*8);
    }
    CP_COMMIT();

    auto issueKV=[&](int kt2){
        uint32_t buf = (kt2&1)*16384u;
#pragma unroll
        for(int t=0;t<4;t++){
            int idx=t*256+tid;
            int r=idx>>3, c=idx&7;
            uint32_t off = r*128 + 16*(c ^ (r&7));
            cp16(sb + AK + buf + off, K + (size_t)(kt2*128+r)*DH + c*8);
            cp16(sb + AV + buf + off, V + (size_t)(kt2*128+r)*DH + c*8);
        }
        CP_COMMIT();
    };
    issueKV(0);

    int nkt2 = qt+1;

    // block-level padding flag over the whole key range (once)
    if(tid==0) *flagp = 0;
    __syncthreads();
    {
        int npad = nkt2*128;
        unsigned a=0;
        for(int i=tid*4; i<npad; i+=1024)
            a |= *(const unsigned*)(pad + b*L_ + i);
        a = __reduce_or_sync(0xffffffffu, a);
        if((tid&31)==0 && a) atomicOr(flagp, 1);
    }
    __syncthreads();
    bool haspad = (*flagp) != 0;

    int l7=lane&7, g8=(lane>>3)&1, g16=lane>>4;
    int rqa = warp*16 + l7 + g8*8;
    uint32_t qOff = AQ + rqa*128;  int qSwz = rqa&7;
    // K fragment base: unit nu (0..7) row = nu*16 + l7 + g16*8
    uint32_t kBase = AK + (uint32_t)(l7 + g16*8)*128;
    int kSwzB = (l7 + g16*8) & 7;          // (row&7) is invariant under +16
    // V fragment base: key group ks (0..7) row = ks*16 + l7 + g8*8
    uint32_t vBase = AV + (uint32_t)(l7 + g8*8)*128;
    int vSwzB = (l7 + g8*8) & 7;
    int rq0 = lane>>2;

    const unsigned onesf[2] = {0x3C003C00u, 0x3C003C00u};  // B = ones (fp16 1.0)

    float m_[2]={-1e30f,-1e30f}, l_[2]={0.f,0.f};
    float o[8][4];
#pragma unroll
    for(int i=0;i<8;i++){o[i][0]=0.f;o[i][1]=0.f;o[i][2]=0.f;o[i][3]=0.f;}
    int r0g = qt*128 + warp*16 + rq0;
    int r1g = r0g + 8;

    for(int kt2=0;kt2<nkt2;kt2++){
        __syncthreads();                 // all warps done with buffer (kt2+1)&1
        if(kt2+1<nkt2){ issueKV(kt2+1); CP_WAIT1(); }
        else          { CP_WAIT0(); }
        if(haspad && warp==1){
#pragma unroll
            for(int j=0;j<4;j++){
                int idx = lane*4 + j;
                spad[idx] = pad[b*L_ + kt2*128 + idx] ? NEG : 0.f;
            }
        }
        __syncthreads();                 // KV(kt2) + spad visible
        uint32_t buf = (kt2&1)*16384u;
        bool diag = (kt2 == qt);

        // ---- S = Q K^T over all 128 keys (16 n8 tiles) ----
        float s[16][4];
#pragma unroll
        for(int i=0;i<16;i++){s[i][0]=0.f;s[i][1]=0.f;s[i][2]=0.f;s[i][3]=0.f;}
#pragma unroll
        for(int ks=0;ks<4;ks++){
            unsigned af[4];
            ldsm_x4(af, sb + qOff + 16*((2*ks + g16) ^ qSwz));
#pragma unroll
            for(int nu=0;nu<8;nu++){
                unsigned bf[4];
                ldsm_x4(bf, sb + kBase + buf + nu*2048u + 16*((2*ks + g8) ^ kSwzB));
                mma16(s[2*nu+0], af, &bf[0]);
                mma16(s[2*nu+1], af, &bf[2]);
            }
        }

        // ---- mask + row max over 128 keys ----
        float rmax0=-1e30f, rmax1=-1e30f;
        if(diag){
            int cbase = kt2*128;
            if(haspad){
#pragma unroll
                for(int nt=0;nt<16;nt++){
                    int cl = nt*8 + 2*(lane&3);
                    int c0 = cbase + cl, c1 = c0+1;
                    float ms0=spad[cl], ms1=spad[cl+1];
                    float v0=s[nt][0] - ms0; if(c0>r0g) v0-=NEG;
                    float v1=s[nt][1] - ms1; if(c1>r0g) v1-=NEG;
                    float v2=s[nt][2] - ms0; if(c0>r1g) v2-=NEG;
                    float v3=s[nt][3] - ms1; if(c1>r1g) v3-=NEG;
                    s[nt][0]=v0; s[nt][1]=v1; s[nt][2]=v2; s[nt][3]=v3;
                    rmax0=fmaxf(rmax0,fmaxf(v0,v1));
                    rmax1=fmaxf(rmax1,fmaxf(v2,v3));
                }
            } else {
#pragma unroll
                for(int nt=0;nt<16;nt++){
                    int cl = nt*8 + 2*(lane&3);
                    int c0 = cbase + cl, c1 = c0+1;
                    float v0=s[nt][0]; if(c0>r0g) v0-=NEG;
                    float v1=s[nt][1]; if(c1>r0g) v1-=NEG;
                    float v2=s[nt][2]; if(c0>r1g) v2-=NEG;
                    float v3=s[nt][3]; if(c1>r1g) v3-=NEG;
                    s[nt][0]=v0; s[nt][1]=v1; s[nt][2]=v2; s[nt][3]=v3;
                    rmax0=fmaxf(rmax0,fmaxf(v0,v1));
                    rmax1=fmaxf(rmax1,fmaxf(v2,v3));
                }
            }
        } else {
            if(haspad){
#pragma unroll
                for(int nt=0;nt<16;nt++){
                    int cl = nt*8 + 2*(lane&3);
                    float ms0=spad[cl], ms1=spad[cl+1];
                    float v0=s[nt][0] - ms0;
                    float v1=s[nt][1] - ms1;
                    float v2=s[nt][2] - ms0;
                    float v3=s[nt][3] - ms1;
                    s[nt][0]=v0; s[nt][1]=v1; s[nt][2]=v2; s[nt][3]=v3;
                    rmax0=fmaxf(rmax0,fmaxf(v0,v1));
                    rmax1=fmaxf(rmax1,fmaxf(v2,v3));
                }
            } else {
#pragma unroll
                for(int nt=0;nt<16;nt++){
                    rmax0=fmaxf(rmax0,fmaxf(s[nt][0],s[nt][1]));
                    rmax1=fmaxf(rmax1,fmaxf(s[nt][2],s[nt][3]));
                }
            }
        }

        // ---- packed half2 max reduce (2 shfl) ----
        rmax0 = fmaxf(rmax0, -60000.f);
        rmax1 = fmaxf(rmax1, -60000.f);
        half2 mh = __floats2half2_rn(rmax0, rmax1);
        unsigned mu = *(unsigned*)&mh;
        unsigned ms1_ = __shfl_xor_sync(0xffffffffu, mu, 1);
        mh = __hmax2(mh, *(half2*)&ms1_);
        mu = *(unsigned*)&mh;
        unsigned ms2_ = __shfl_xor_sync(0xffffffffu, mu, 2);
        mh = __hmax2(mh, *(half2*)&ms2_);
        float2 rmf = __half22float2(mh);

        float mn0=fmaxf(m_[0],rmf.x), mn1=fmaxf(m_[1],rmf.y);
        float corr0=fexp2(m_[0]-mn0), corr1=fexp2(m_[1]-mn1);
        m_[0]=mn0; m_[1]=mn1;

        // ---- exp2 in f16x2 -> P stays in registers (s dies here) ----
        unsigned eh01[16], eh23[16];
#pragma unroll
        for(int nt=0;nt<16;nt++){
            half2 e01 = h2exp2(__floats2half2_rn(s[nt][0]-mn0, s[nt][1]-mn0));
            half2 e23 = h2exp2(__floats2half2_rn(s[nt][2]-mn1, s[nt][3]-mn1));
            eh01[nt] = *(unsigned*)&e01;
            eh23[nt] = *(unsigned*)&e23;
        }
#pragma unroll
        for(int nt=0;nt<8;nt++){
            o[nt][0]*=corr0; o[nt][1]*=corr0;
            o[nt][2]*=corr1; o[nt][3]*=corr1;
        }

        // ---- O += P V over 128 keys ; row sums via P*ones MMA ----
        float lsum[4]={0.f,0.f,0.f,0.f};
#pragma unroll
        for(int ks=0;ks<8;ks++){
            unsigned pf[4] = {eh01[2*ks], eh23[2*ks], eh01[2*ks+1], eh23[2*ks+1]};
            mma16(lsum, pf, onesf);
            uint32_t vb = vBase + buf + ks*2048u;
#pragma unroll
            for(int ntp=0;ntp<4;ntp++){
                unsigned bf[4];
                ldsm_x4t(bf, sb + vb + 16*((2*ntp + g16) ^ vSwzB));
                mma16(o[2*ntp+0], pf, &bf[0]);
                mma16(o[2*ntp+1], pf, &bf[2]);
            }
        }
        l_[0]=l_[0]*corr0+lsum[0];
        l_[1]=l_[1]*corr1+lsum[2];
    }

    // ---- normalize + write half [B,L,D] ----
    float inv0=1.f/l_[0], inv1=1.f/l_[1];
#pragma unroll
    for(int nt=0;nt<8;nt++){
        int dd = nt*8 + 2*(lane&3);
        *(half2*)&outp[(size_t)(b*L_+r0g)*D_ + h*DH + dd] =
            __floats2half2_rn(o[nt][0]*inv0, o[nt][1]*inv0);
        *(half2*)&outp[(size_t)(b*L_+r1g)*D_ + h*DH + dd] =
            __floats2half2_rn(o[nt][2]*inv1, o[nt][3]*inv1);
    }
}

// -------------------- launch --------------------
extern "C" void kernel_launch(void* const* d_in, const int* in_sizes, int n_in,
                              void* d_out, int out_size) {
    const float* q  = (const float*)d_in[0];
    const float* k  = (const float*)d_in[1];
    const float* v  = (const float*)d_in[2];
    const unsigned char* pad = (const unsigned char*)d_in[3];
    const float* Wq = (const float*)d_in[4];
    const float* bq = (const float*)d_in[5];
    const float* Wk = (const float*)d_in[6];
    const float* bk = (const float*)d_in[7];
    const float* Wv = (const float*)d_in[8];
    const float* bv = (const float*)d_in[9];
    const float* Wo = (const float*)d_in[10];
    const float* bo = (const float*)d_in[11];
    float* out = (float*)d_out;

    __half *p_qpe, *p_kpe, *p_vr, *p_Qh, *p_Kh, *p_Vh, *p_attn, *p_Wt;
    cudaGetSymbolAddress((void**)&p_qpe,  g_qpe);
    cudaGetSymbolAddress((void**)&p_kpe,  g_kpe);
    cudaGetSymbolAddress((void**)&p_vr,   g_vr);
    cudaGetSymbolAddress((void**)&p_Qh,   g_Qh);
    cudaGetSymbolAddress((void**)&p_Kh,   g_Kh);
    cudaGetSymbolAddress((void**)&p_Vh,   g_Vh);
    cudaGetSymbolAddress((void**)&p_attn, g_attn);
    cudaGetSymbolAddress((void**)&p_Wt,   g_Wt);

    cudaFuncSetAttribute(attn_h, cudaFuncAttributeMaxDynamicSharedMemorySize, ATTN_SMEM);
    cudaFuncSetAttribute(gemm_h5<0>, cudaFuncAttributeMaxDynamicSharedMemorySize, G_SMEM);
    cudaFuncSetAttribute(gemm_h5<1>, cudaFuncAttributeMaxDynamicSharedMemorySize, G_SMEM);

    // 0) weight transposes -> half [N][K]
    transpose_w4<<<dim3(32,32,4), dim3(32,8)>>>(Wq, Wk, Wv, Wo);

    // 1) positional encodings -> half
    int pe_threads = M_ * NF_;
    pe_add_kernel<<<(pe_threads + 255) / 256, 256>>>(q, k, v);

    // 2) fused QKV projections -> head layout (half); Q pre-scaled by 0.125*log2e
    gemm_h5<1><<<dim3(8, 64, 3), 128, G_SMEM>>>(
        p_qpe, p_kpe, p_vr, p_Wt, bq, bk, bv,
        (void*)p_Qh, (void*)p_Kh, (void*)p_Vh, 0.18033688f);

    // 3) fused causal flash attention (single 128-key softmax pass)
    attn_h<<<dim3(L_ / 128, B_ * H_), 256, ATTN_SMEM>>>(pad, p_attn);

    // 4) output projection -> fp32 d_out
    gemm_h5<0><<<dim3(8, 64, 1), 128, G_SMEM>>>(
        p_attn, nullptr, nullptr, p_Wt, bo, nullptr, nullptr,
        (void*)out, nullptr, nullptr, 1.0f);
}

// round 16
// speedup vs baseline: 1.0370x; 1.0180x over previous
#include <cuda_runtime.h>
#include <cuda_fp16.h>
#include <math.h>
#include <stdint.h>

#define B_  4
#define L_  2048
#define D_  1024
#define H_  16
#define DH  64
#define M_  (B_*L_)        /* 8192 */
#define NF_ (D_/2)         /* 512 */
#define NEG 1e7f

// -------------------- scratch --------------------
__device__ __half g_qpe[M_*D_];
__device__ __half g_kpe[M_*D_];
__device__ __half g_vr [M_*D_];
__device__ __half g_Qh[M_*D_];    // [B,H,L,DH]  (Q pre-scaled by 0.125*log2e)
__device__ __half g_Kh[M_*D_];
__device__ __half g_Vh[M_*D_];
__device__ __half g_attn[M_*D_];  // [B,L,D]
__device__ __half g_Wt[4*D_*D_];  // transposed weights [N][K]

// -------------------- helpers --------------------
__device__ __forceinline__ void mma16(float* c, const unsigned* a, const unsigned* b){
    asm volatile("mma.sync.aligned.m16n8k16.row.col.f32.f16.f16.f32 "
        "{%0,%1,%2,%3}, {%4,%5,%6,%7}, {%8,%9}, {%0,%1,%2,%3};"
        : "+f"(c[0]),"+f"(c[1]),"+f"(c[2]),"+f"(c[3])
        : "r"(a[0]),"r"(a[1]),"r"(a[2]),"r"(a[3]),"r"(b[0]),"r"(b[1]));
}
__device__ __forceinline__ void ldsm_x4(unsigned* r, uint32_t a){
    asm volatile("ldmatrix.sync.aligned.m8n8.x4.shared.b16 {%0,%1,%2,%3}, [%4];"
        : "=r"(r[0]),"=r"(r[1]),"=r"(r[2]),"=r"(r[3]) : "r"(a));
}
__device__ __forceinline__ void ldsm_x4t(unsigned* r, uint32_t a){
    asm volatile("ldmatrix.sync.aligned.m8n8.x4.trans.shared.b16 {%0,%1,%2,%3}, [%4];"
        : "=r"(r[0]),"=r"(r[1]),"=r"(r[2]),"=r"(r[3]) : "r"(a));
}
__device__ __forceinline__ uint32_t smem_u32(const void* p){
    uint32_t a; asm("{ .reg .u64 t; cvta.to.shared.u64 t, %1; cvt.u32.u64 %0, t; }"
                    : "=r"(a) : "l"(p)); return a;
}
__device__ __forceinline__ void cp16(uint32_t dst, const void* src){
    asm volatile("cp.async.cg.shared.global [%0], [%1], 16;" :: "r"(dst), "l"(src));
}
#define CP_COMMIT() asm volatile("cp.async.commit_group;" ::: "memory")
#define CP_WAIT1()  asm volatile("cp.async.wait_group 1;" ::: "memory")
#define CP_WAIT0()  asm volatile("cp.async.wait_group 0;" ::: "memory")
__device__ __forceinline__ float fexp2(float x){
    float y; asm("ex2.approx.ftz.f32 %0, %1;" : "=f"(y) : "f"(x)); return y;
}

// -------------------- PE add (fp32 math -> half) --------------------
__global__ void pe_add_kernel(const float* __restrict__ q, const float* __restrict__ k,
                              const float* __restrict__ v) {
    int i = blockIdx.x * blockDim.x + threadIdx.x;
    if (i >= M_ * NF_) return;
    int row = i / NF_;
    int f   = i - row * NF_;
    int l   = row & (L_ - 1);
    const float kC = 9.210340371976184f / 512.0f;
    float ang = (float)l * expf(-(float)f * kC);
    float s, c;
    sincosf(ang, &s, &c);
    int base = row * D_ + 2 * f;
    *(half2*)&g_qpe[base] = __floats2half2_rn(q[base] + s, q[base+1] + c);
    *(half2*)&g_kpe[base] = __floats2half2_rn(k[base] + s, k[base+1] + c);
    *(half2*)&g_vr[base]  = __floats2half2_rn(v[base],     v[base+1]);
}

// -------------------- weight transpose -> half [N][K] --------------------
__global__ void transpose_w4(const float* __restrict__ W0, const float* __restrict__ W1,
                             const float* __restrict__ W2, const float* __restrict__ W3){
    __shared__ float t[32][33];
    const float* W = (blockIdx.z==0)?W0:(blockIdx.z==1)?W1:(blockIdx.z==2)?W2:W3;
    __half* O = g_Wt + (size_t)blockIdx.z * D_ * D_;
    int x0 = blockIdx.x*32, y0 = blockIdx.y*32;
    int tx = threadIdx.x, ty0 = threadIdx.y;   // (32, 8)
#pragma unroll
    for (int i=0;i<4;i++){ int ty=ty0+i*8; t[ty][tx] = W[(size_t)(y0+ty)*D_ + x0+tx]; }
    __syncthreads();
#pragma unroll
    for (int i=0;i<2;i++){
        int kk = ty0 + i*8;
        half2 h = __floats2half2_rn(t[2*kk][tx], t[2*kk+1][tx]);
        *(half2*)&O[(size_t)(x0+tx)*D_ + y0 + 2*kk] = h;
    }
}

// -------------------- fp16 GEMM: BK=64, 3-stage cp.async, optional QKV fusion -----
#define GS 32768
#define G_SMEM (3*GS)

template<int QKV>
__global__ void __launch_bounds__(128, 2)
gemm_h5(const __half* __restrict__ A0, const __half* __restrict__ A1,
        const __half* __restrict__ A2, const __half* __restrict__ WtBase,
        const float* __restrict__ b0, const float* __restrict__ b1,
        const float* __restrict__ b2,
        void* O0, void* O1, void* O2, float qs){
    extern __shared__ __align__(128) char smem[];
    uint32_t sb = smem_u32(smem);
    int z = QKV ? blockIdx.z : 0;
    const __half* A    = (z==0)?A0:(z==1)?A1:A2;
    const __half* Wt   = WtBase + (size_t)(QKV ? z : 3) * D_ * D_;
    const float*  bias = (z==0)?b0:(z==1)?b1:b2;
    void* Cv           = (z==0)?O0:(z==1)?O1:O2;
    float oscale       = (QKV && z==0) ? qs : 1.f;

    int tid=threadIdx.x, lane=tid&31;
    int warp=tid>>5, wm=warp>>1, wn=warp&1;
    int bm=blockIdx.y*128, bn=blockIdx.x*128;

    const __half* Ab = A  + (size_t)bm * D_;
    const __half* Bb = Wt + (size_t)bn * D_;

    float acc[4][8][4];
#pragma unroll
    for(int i=0;i<4;i++)
#pragma unroll
      for(int j=0;j<8;j++)
#pragma unroll
        for(int r=0;r<4;r++) acc[i][j][r]=0.f;

    int prr = tid>>3, prc = tid&7;
    uint32_t stoff[8]; int prow[8];
#pragma unroll
    for(int it=0;it<8;it++){
        int r = prr + 16*it;
        prow[it] = r;
        stoff[it] = r*128 + 16*(prc ^ (r&7));
    }

    int l7=lane&7, g8=(lane>>3)&1, g16=lane>>4;
    uint32_t aRow[4]; int aSwz[4];
#pragma unroll
    for(int mt=0;mt<4;mt++){
        int r = wm*64 + mt*16 + l7 + g8*8;
        aRow[mt] = r*128; aSwz[mt] = r&7;
    }
    uint32_t bRow[4]; int bSwz[4];
#pragma unroll
    for(int ntp=0;ntp<4;ntp++){
        int n = wn*64 + ntp*16 + l7 + g16*8;
        bRow[ntp] = 16384u + n*128; bSwz[ntp] = n&7;
    }

    auto issue=[&](int ch){
        int s = ch % 3;
        uint32_t da = sb + s*GS;
#pragma unroll
        for(int it=0;it<8;it++){
            cp16(da + stoff[it],          Ab + (size_t)prow[it]*D_ + ch*64 + prc*8);
            cp16(da + 16384 + stoff[it],  Bb + (size_t)prow[it]*D_ + ch*64 + prc*8);
        }
        CP_COMMIT();
    };

    issue(0); issue(1);

    for(int ch=0; ch<16; ch++){
        if(ch<15) CP_WAIT1(); else CP_WAIT0();
        __syncthreads();
        if(ch+2<16) issue(ch+2);
        uint32_t so = sb + (ch%3)*GS;
#pragma unroll
        for(int ks=0;ks<4;ks++){
            unsigned bf[4][4];
#pragma unroll
            for(int ntp=0;ntp<4;ntp++)
                ldsm_x4(bf[ntp], so + bRow[ntp] + 16*((2*ks+g8)^bSwz[ntp]));
#pragma unroll
            for(int mt=0;mt<4;mt++){
                unsigned af[4];
                ldsm_x4(af, so + aRow[mt] + 16*((2*ks+g16)^aSwz[mt]));
#pragma unroll
                for(int ntp=0;ntp<4;ntp++){
                    mma16(acc[mt][2*ntp+0], af, &bf[ntp][0]);
                    mma16(acc[mt][2*ntp+1], af, &bf[ntp][2]);
                }
            }
        }
    }

#pragma unroll
    for(int mt=0;mt<4;mt++){
        int r0 = bm + wm*64 + mt*16 + (lane>>2);
#pragma unroll
        for(int hf=0;hf<2;hf++){
            int m = r0 + hf*8;
            int bidx = m>>11, l = m&(L_-1);
#pragma unroll
            for(int nt=0;nt<8;nt++){
                int n = bn + wn*64 + nt*8 + 2*(lane&3);
                float2 bb = *(const float2*)&bias[n];
                float v0 = (acc[mt][nt][hf*2+0] + bb.x) * oscale;
                float v1 = (acc[mt][nt][hf*2+1] + bb.y) * oscale;
                if(QKV){
                    int h=n>>6, dd=n&63;
                    *(half2*)&((__half*)Cv)[(size_t)((bidx*H_+h)*L_+l)*DH + dd] =
                        __floats2half2_rn(v0, v1);
                } else {
                    float2 ov = make_float2(v0, v1);
                    *(float2*)&((float*)Cv)[(size_t)m*D_ + n] = ov;
                }
            }
        }
    }
}

// -------------------- fp16 flash attention v7: key-split warp specialization -----
// 64-row Q tiles; 8 warps = 4 row-groups x 2 key-halves. Per 128-key chunk each
// warp runs ONE R11-style 64-key softmax pass on its key half (independent m/l/O
// per half, merged once at the end). K/V fragments read by 4 warps instead of 8.
// Fully-causally-masked half-chunks skipped with one warp-uniform branch.
#define AQ 0                 /* 8KB  (64 rows) */
#define AK 8192              /* 2 x 16KB */
#define AV 40960             /* 2 x 16KB */
#define APAD 73728           /* 128 floats */
#define AFLAG (APAD + 512)
#define ATTN_SMEM (AFLAG + 16)

__global__ void __launch_bounds__(256, 2)
attn_h(const unsigned char* __restrict__ pad, __half* __restrict__ outp){
    extern __shared__ __align__(128) char smem[];
    uint32_t sb = smem_u32(smem);
    float* spad = (float*)(smem + APAD);
    int* flagp  = (int*)(smem + AFLAG);

    int tid=threadIdx.x, lane=tid&31, warp=tid>>5;
    int rgrp = warp & 3, kh = warp >> 2;
    int qt = (int)(gridDim.x - 1) - (int)blockIdx.x;   // 0..31, long blocks first
    int bh=blockIdx.y;
    int b=bh>>4, h=bh&15;
    const __half* Q = g_Qh + (size_t)bh*L_*DH;
    const __half* K = g_Kh + (size_t)bh*L_*DH;
    const __half* V = g_Vh + (size_t)bh*L_*DH;

    // async load Q tile: 64 rows x 8 chunks (512 cp16)
#pragma unroll
    for(int t=0;t<2;t++){
        int idx=t*256+tid;
        int r=idx>>3, c=idx&7;
        cp16(sb + AQ + r*128 + 16*(c ^ (r&7)),
             Q + (size_t)(qt*64+r)*DH + c*8);
    }
    CP_COMMIT();

    auto issueKV=[&](int kt2){
        uint32_t buf = (kt2&1)*16384u;
#pragma unroll
        for(int t=0;t<4;t++){
            int idx=t*256+tid;
            int r=idx>>3, c=idx&7;
            uint32_t off = r*128 + 16*(c ^ (r&7));
            cp16(sb + AK + buf + off, K + (size_t)(kt2*128+r)*DH + c*8);
            cp16(sb + AV + buf + off, V + (size_t)(kt2*128+r)*DH + c*8);
        }
        CP_COMMIT();
    };
    issueKV(0);

    int row_min = qt*64;
    int nkt2 = (qt*64 + 63)/128 + 1;

    // block-level padding flag over the whole key range (once)
    if(tid==0) *flagp = 0;
    __syncthreads();
    {
        int npad = nkt2*128;
        unsigned a=0;
        for(int i=tid*4; i<npad; i+=1024)
            a |= *(const unsigned*)(pad + b*L_ + i);
        a = __reduce_or_sync(0xffffffffu, a);
        if((tid&31)==0 && a) atomicOr(flagp, 1);
    }
    __syncthreads();
    bool haspad = (*flagp) != 0;

    int l7=lane&7, g8=(lane>>3)&1, g16=lane>>4;
    int rqa = rgrp*16 + l7 + g8*8;
    uint32_t qOff = AQ + rqa*128;  int qSwz = rqa&7;
    // K fragment base (warp's 64-key half): unit ntp row = kh*64 + ntp*16 + l7 + g16*8
    uint32_t kBase = AK + (uint32_t)(kh*64 + l7 + g16*8)*128;
    int kSwzB = (l7 + g16*8) & 7;
    // V fragment base: key group ks row = kh*64 + ks*16 + l7 + g8*8
    uint32_t vBase = AV + (uint32_t)(kh*64 + l7 + g8*8)*128;
    int vSwzB = (l7 + g8*8) & 7;
    int rq0 = lane>>2;

    const unsigned onesf[2] = {0x3C003C00u, 0x3C003C00u};

    float m_[2]={-1e30f,-1e30f}, l_[2]={0.f,0.f};
    float o[8][4];
#pragma unroll
    for(int i=0;i<8;i++){o[i][0]=0.f;o[i][1]=0.f;o[i][2]=0.f;o[i][3]=0.f;}
    int r0g = qt*64 + rgrp*16 + rq0;
    int r1g = r0g + 8;

    for(int kt2=0;kt2<nkt2;kt2++){
        __syncthreads();
        if(kt2+1<nkt2){ issueKV(kt2+1); CP_WAIT1(); }
        else          { CP_WAIT0(); }
        if(haspad && warp==1){
#pragma unroll
            for(int j=0;j<4;j++){
                int idx = lane*4 + j;
                spad[idx] = pad[b*L_ + kt2*128 + idx] ? NEG : 0.f;
            }
        }
        __syncthreads();
        uint32_t buf = (kt2&1)*16384u;
        int c0 = kt2*128 + kh*64;          // warp's key base
        if(c0 > row_min) continue;          // fully causally masked: contributes 0
        bool diag = (c0 == row_min);
        const float* sp = spad + kh*64;

        // ---- S = Q K^T over warp's 64 keys ----
        float s[8][4];
#pragma unroll
        for(int i=0;i<8;i++){s[i][0]=0.f;s[i][1]=0.f;s[i][2]=0.f;s[i][3]=0.f;}
#pragma unroll
        for(int ks=0;ks<4;ks++){
            unsigned af[4];
            ldsm_x4(af, sb + qOff + 16*((2*ks + g16) ^ qSwz));
#pragma unroll
            for(int ntp=0;ntp<4;ntp++){
                unsigned bf[4];
                ldsm_x4(bf, sb + kBase + buf + ntp*2048u + 16*((2*ks + g8) ^ kSwzB));
                mma16(s[2*ntp+0], af, &bf[0]);
                mma16(s[2*ntp+1], af, &bf[2]);
            }
        }

        // ---- mask + row max ----
        float rmax0=-1e30f, rmax1=-1e30f;
        if(diag){
            if(haspad){
#pragma unroll
                for(int nt=0;nt<8;nt++){
                    int cl = nt*8 + 2*(lane&3);
                    int cg0 = c0 + cl, cg1 = cg0+1;
                    float ms0=sp[cl], ms1=sp[cl+1];
                    float v0=s[nt][0] - ms0; if(cg0>r0g) v0-=NEG;
                    float v1=s[nt][1] - ms1; if(cg1>r0g) v1-=NEG;
                    float v2=s[nt][2] - ms0; if(cg0>r1g) v2-=NEG;
                    float v3=s[nt][3] - ms1; if(cg1>r1g) v3-=NEG;
                    s[nt][0]=v0; s[nt][1]=v1; s[nt][2]=v2; s[nt][3]=v3;
                    rmax0=fmaxf(rmax0,fmaxf(v0,v1));
                    rmax1=fmaxf(rmax1,fmaxf(v2,v3));
                }
            } else {
#pragma unroll
                for(int nt=0;nt<8;nt++){
                    int cl = nt*8 + 2*(lane&3);
                    int cg0 = c0 + cl, cg1 = cg0+1;
                    float v0=s[nt][0]; if(cg0>r0g) v0-=NEG;
                    float v1=s[nt][1]; if(cg1>r0g) v1-=NEG;
                    float v2=s[nt][2]; if(cg0>r1g) v2-=NEG;
                    float v3=s[nt][3]; if(cg1>r1g) v3-=NEG;
                    s[nt][0]=v0; s[nt][1]=v1; s[nt][2]=v2; s[nt][3]=v3;
                    rmax0=fmaxf(rmax0,fmaxf(v0,v1));
                    rmax1=fmaxf(rmax1,fmaxf(v2,v3));
                }
            }
        } else {
            if(haspad){
#pragma unroll
                for(int nt=0;nt<8;nt++){
                    int cl = nt*8 + 2*(lane&3);
                    float ms0=sp[cl], ms1=sp[cl+1];
                    float v0=s[nt][0] - ms0;
                    float v1=s[nt][1] - ms1;
                    float v2=s[nt][2] - ms0;
                    float v3=s[nt][3] - ms1;
                    s[nt][0]=v0; s[nt][1]=v1; s[nt][2]=v2; s[nt][3]=v3;
                    rmax0=fmaxf(rmax0,fmaxf(v0,v1));
                    rmax1=fmaxf(rmax1,fmaxf(v2,v3));
                }
            } else {
#pragma unroll
                for(int nt=0;nt<8;nt++){
                    rmax0=fmaxf(rmax0,fmaxf(s[nt][0],s[nt][1]));
                    rmax1=fmaxf(rmax1,fmaxf(s[nt][2],s[nt][3]));
                }
            }
        }

        // ---- packed half2 max reduce (2 shfl) ----
        rmax0 = fmaxf(rmax0, -60000.f);
        rmax1 = fmaxf(rmax1, -60000.f);
        half2 mh = __floats2half2_rn(rmax0, rmax1);
        unsigned mu = *(unsigned*)&mh;
        unsigned ms1_ = __shfl_xor_sync(0xffffffffu, mu, 1);
        mh = __hmax2(mh, *(half2*)&ms1_);
        mu = *(unsigned*)&mh;
        unsigned ms2_ = __shfl_xor_sync(0xffffffffu, mu, 2);
        mh = __hmax2(mh, *(half2*)&ms2_);
        float2 rmf = __half22float2(mh);

        float mn0=fmaxf(m_[0],rmf.x), mn1=fmaxf(m_[1],rmf.y);
        float corr0=fexp2(m_[0]-mn0), corr1=fexp2(m_[1]-mn1);
        m_[0]=mn0; m_[1]=mn1;

        // ---- exp2 in f16x2 -> P stays in registers ----
        unsigned eh01[8], eh23[8];
#pragma unroll
        for(int nt=0;nt<8;nt++){
            half2 e01 = h2exp2(__floats2half2_rn(s[nt][0]-mn0, s[nt][1]-mn0));
            half2 e23 = h2exp2(__floats2half2_rn(s[nt][2]-mn1, s[nt][3]-mn1));
            eh01[nt] = *(unsigned*)&e01;
            eh23[nt] = *(unsigned*)&e23;
        }
#pragma unroll
        for(int nt=0;nt<8;nt++){
            o[nt][0]*=corr0; o[nt][1]*=corr0;
            o[nt][2]*=corr1; o[nt][3]*=corr1;
        }

        // ---- O += P V ; row sums via P*ones MMA ----
        float lsum[4]={0.f,0.f,0.f,0.f};
#pragma unroll
        for(int ks=0;ks<4;ks++){
            unsigned pf[4] = {eh01[2*ks], eh23[2*ks], eh01[2*ks+1], eh23[2*ks+1]};
            mma16(lsum, pf, onesf);
            uint32_t vb = vBase + buf + ks*2048u;
#pragma unroll
            for(int ntp=0;ntp<4;ntp++){
                unsigned bf[4];
                ldsm_x4t(bf, sb + vb + 16*((2*ntp + g16) ^ vSwzB));
                mma16(o[2*ntp+0], pf, &bf[0]);
                mma16(o[2*ntp+1], pf, &bf[2]);
            }
        }
        l_[0]=l_[0]*corr0+lsum[0];
        l_[1]=l_[1]*corr1+lsum[2];
    }

    // ---- cross-half merge: kh=1 stages (m,l,O) in smem; kh=0 combines ----
    __syncthreads();                       // KV buffers dead; reuse as staging
    if(kh==1){
        uint32_t obase = sb + AK + rgrp*4096u + lane*128u;
#pragma unroll
        for(int nt=0;nt<8;nt++){
            float4 v = make_float4(o[nt][0], o[nt][1], o[nt][2], o[nt][3]);
            *(float4*)(uintptr_t)0;        // placeholder removed below
            // store with light swizzle
            *(float4*)(smem + AK + rgrp*4096 + lane*128 + 16*(nt ^ (lane&7))) = v;
        }
        *(float4*)(smem + AV + rgrp*512 + lane*16) =
            make_float4(m_[0], m_[1], l_[0], l_[1]);
    }
    __syncthreads();
    if(kh==0){
        float4 ml = *(const float4*)(smem + AV + rgrp*512 + lane*16);
        float M0 = fmaxf(m_[0], ml.x), M1 = fmaxf(m_[1], ml.y);
        float ca0 = fexp2(m_[0]-M0), cb0 = fexp2(ml.x-M0);
        float ca1 = fexp2(m_[1]-M1), cb1 = fexp2(ml.y-M1);
        float L0 = l_[0]*ca0 + ml.z*cb0;
        float L1 = l_[1]*ca1 + ml.w*cb1;
        float inv0 = 1.f/L0, inv1 = 1.f/L1;
#pragma unroll
        for(int nt=0;nt<8;nt++){
            float4 ov = *(const float4*)(smem + AK + rgrp*4096 + lane*128 + 16*(nt ^ (lane&7)));
            float r0 = (o[nt][0]*ca0 + ov.x*cb0) * inv0;
            float r1 = (o[nt][1]*ca0 + ov.y*cb0) * inv0;
            float r2 = (o[nt][2]*ca1 + ov.z*cb1) * inv1;
            float r3 = (o[nt][3]*ca1 + ov.w*cb1) * inv1;
            int dd = nt*8 + 2*(lane&3);
            *(half2*)&outp[(size_t)(b*L_+r0g)*D_ + h*DH + dd] = __floats2half2_rn(r0, r1);
            *(half2*)&outp[(size_t)(b*L_+r1g)*D_ + h*DH + dd] = __floats2half2_rn(r2, r3);
        }
    }
}

// -------------------- launch --------------------
extern "C" void kernel_launch(void* const* d_in, const int* in_sizes, int n_in,
                              void* d_out, int out_size) {
    const float* q  = (const float*)d_in[0];
    const float* k  = (const float*)d_in[1];
    const float* v  = (const float*)d_in[2];
    const unsigned char* pad = (const unsigned char*)d_in[3];
    const float* Wq = (const float*)d_in[4];
    const float* bq = (const float*)d_in[5];
    const float* Wk = (const float*)d_in[6];
    const float* bk = (const float*)d_in[7];
    const float* Wv = (const float*)d_in[8];
    const float* bv = (const float*)d_in[9];
    const float* Wo = (const float*)d_in[10];
    const float* bo = (const float*)d_in[11];
    float* out = (float*)d_out;

    __half *p_qpe, *p_kpe, *p_vr, *p_Qh, *p_Kh, *p_Vh, *p_attn, *p_Wt;
    cudaGetSymbolAddress((void**)&p_qpe,  g_qpe);
    cudaGetSymbolAddress((void**)&p_kpe,  g_kpe);
    cudaGetSymbolAddress((void**)&p_vr,   g_vr);
    cudaGetSymbolAddress((void**)&p_Qh,   g_Qh);
    cudaGetSymbolAddress((void**)&p_Kh,   g_Kh);
    cudaGetSymbolAddress((void**)&p_Vh,   g_Vh);
    cudaGetSymbolAddress((void**)&p_attn, g_attn);
    cudaGetSymbolAddress((void**)&p_Wt,   g_Wt);

    cudaFuncSetAttribute(attn_h, cudaFuncAttributeMaxDynamicSharedMemorySize, ATTN_SMEM);
    cudaFuncSetAttribute(gemm_h5<0>, cudaFuncAttributeMaxDynamicSharedMemorySize, G_SMEM);
    cudaFuncSetAttribute(gemm_h5<1>, cudaFuncAttributeMaxDynamicSharedMemorySize, G_SMEM);

    // 0) weight transposes -> half [N][K]
    transpose_w4<<<dim3(32,32,4), dim3(32,8)>>>(Wq, Wk, Wv, Wo);

    // 1) positional encodings -> half
    int pe_threads = M_ * NF_;
    pe_add_kernel<<<(pe_threads + 255) / 256, 256>>>(q, k, v);

    // 2) fused QKV projections -> head layout (half); Q pre-scaled by 0.125*log2e
    gemm_h5<1><<<dim3(8, 64, 3), 128, G_SMEM>>>(
        p_qpe, p_kpe, p_vr, p_Wt, bq, bk, bv,
        (void*)p_Qh, (void*)p_Kh, (void*)p_Vh, 0.18033688f);

    // 3) fused causal flash attention (key-split warp specialization)
    attn_h<<<dim3(L_ / 64, B_ * H_), 256, ATTN_SMEM>>>(pad, p_attn);

    // 4) output projection -> fp32 d_out
    gemm_h5<0><<<dim3(8, 64, 1), 128, G_SMEM>>>(
        p_attn, nullptr, nullptr, p_Wt, bo, nullptr, nullptr,
        (void*)out, nullptr, nullptr, 1.0f);
}

// round 17
// speedup vs baseline: 1.0416x; 1.0045x over previous
#include <cuda_runtime.h>
#include <cuda_fp16.h>
#include <math.h>
#include <stdint.h>

#define B_  4
#define L_  2048
#define D_  1024
#define H_  16
#define DH  64
#define M_  (B_*L_)        /* 8192 */
#define NF_ (D_/2)         /* 512 */
#define NEG 1e7f

// -------------------- scratch --------------------
__device__ __half g_qpe[M_*D_];
__device__ __half g_kpe[M_*D_];
__device__ __half g_vr [M_*D_];
__device__ __half g_Qh[M_*D_];    // [B,H,L,DH]  (Q pre-scaled by 0.125*log2e)
__device__ __half g_Kh[M_*D_];
__device__ __half g_Vh[M_*D_];
__device__ __half g_attn[M_*D_];  // [B,L,D]
__device__ __half g_Wt[4*D_*D_];  // transposed weights [N][K]

// -------------------- helpers --------------------
__device__ __forceinline__ void mma16(float* c, const unsigned* a, const unsigned* b){
    asm volatile("mma.sync.aligned.m16n8k16.row.col.f32.f16.f16.f32 "
        "{%0,%1,%2,%3}, {%4,%5,%6,%7}, {%8,%9}, {%0,%1,%2,%3};"
        : "+f"(c[0]),"+f"(c[1]),"+f"(c[2]),"+f"(c[3])
        : "r"(a[0]),"r"(a[1]),"r"(a[2]),"r"(a[3]),"r"(b[0]),"r"(b[1]));
}
__device__ __forceinline__ void ldsm_x4(unsigned* r, uint32_t a){
    asm volatile("ldmatrix.sync.aligned.m8n8.x4.shared.b16 {%0,%1,%2,%3}, [%4];"
        : "=r"(r[0]),"=r"(r[1]),"=r"(r[2]),"=r"(r[3]) : "r"(a));
}
__device__ __forceinline__ void ldsm_x4t(unsigned* r, uint32_t a){
    asm volatile("ldmatrix.sync.aligned.m8n8.x4.trans.shared.b16 {%0,%1,%2,%3}, [%4];"
        : "=r"(r[0]),"=r"(r[1]),"=r"(r[2]),"=r"(r[3]) : "r"(a));
}
__device__ __forceinline__ uint32_t smem_u32(const void* p){
    uint32_t a; asm("{ .reg .u64 t; cvta.to.shared.u64 t, %1; cvt.u32.u64 %0, t; }"
                    : "=r"(a) : "l"(p)); return a;
}
__device__ __forceinline__ void cp16(uint32_t dst, const void* src){
    asm volatile("cp.async.cg.shared.global [%0], [%1], 16;" :: "r"(dst), "l"(src));
}
#define CP_COMMIT() asm volatile("cp.async.commit_group;" ::: "memory")
#define CP_WAIT1()  asm volatile("cp.async.wait_group 1;" ::: "memory")
#define CP_WAIT0()  asm volatile("cp.async.wait_group 0;" ::: "memory")
__device__ __forceinline__ float fexp2(float x){
    float y; asm("ex2.approx.ftz.f32 %0, %1;" : "=f"(y) : "f"(x)); return y;
}

// -------------------- PE add (fp32 math -> half) --------------------
__global__ void pe_add_kernel(const float* __restrict__ q, const float* __restrict__ k,
                              const float* __restrict__ v) {
    int i = blockIdx.x * blockDim.x + threadIdx.x;
    if (i >= M_ * NF_) return;
    int row = i / NF_;
    int f   = i - row * NF_;
    int l   = row & (L_ - 1);
    const float kC = 9.210340371976184f / 512.0f;
    float ang = (float)l * expf(-(float)f * kC);
    float s, c;
    sincosf(ang, &s, &c);
    int base = row * D_ + 2 * f;
    *(half2*)&g_qpe[base] = __floats2half2_rn(q[base] + s, q[base+1] + c);
    *(half2*)&g_kpe[base] = __floats2half2_rn(k[base] + s, k[base+1] + c);
    *(half2*)&g_vr[base]  = __floats2half2_rn(v[base],     v[base+1]);
}

// -------------------- weight transpose -> half [N][K] --------------------
__global__ void transpose_w4(const float* __restrict__ W0, const float* __restrict__ W1,
                             const float* __restrict__ W2, const float* __restrict__ W3){
    __shared__ float t[32][33];
    const float* W = (blockIdx.z==0)?W0:(blockIdx.z==1)?W1:(blockIdx.z==2)?W2:W3;
    __half* O = g_Wt + (size_t)blockIdx.z * D_ * D_;
    int x0 = blockIdx.x*32, y0 = blockIdx.y*32;
    int tx = threadIdx.x, ty0 = threadIdx.y;   // (32, 8)
#pragma unroll
    for (int i=0;i<4;i++){ int ty=ty0+i*8; t[ty][tx] = W[(size_t)(y0+ty)*D_ + x0+tx]; }
    __syncthreads();
#pragma unroll
    for (int i=0;i<2;i++){
        int kk = ty0 + i*8;
        half2 h = __floats2half2_rn(t[2*kk][tx], t[2*kk+1][tx]);
        *(half2*)&O[(size_t)(x0+tx)*D_ + y0 + 2*kk] = h;
    }
}

// -------------------- fp16 GEMM: BK=64, 3-stage cp.async, optional QKV fusion -----
#define GS 32768
#define G_SMEM (3*GS)

template<int QKV>
__global__ void __launch_bounds__(128, 2)
gemm_h5(const __half* __restrict__ A0, const __half* __restrict__ A1,
        const __half* __restrict__ A2, const __half* __restrict__ WtBase,
        const float* __restrict__ b0, const float* __restrict__ b1,
        const float* __restrict__ b2,
        void* O0, void* O1, void* O2, float qs){
    extern __shared__ __align__(128) char smem[];
    uint32_t sb = smem_u32(smem);
    int z = QKV ? blockIdx.z : 0;
    const __half* A    = (z==0)?A0:(z==1)?A1:A2;
    const __half* Wt   = WtBase + (size_t)(QKV ? z : 3) * D_ * D_;
    const float*  bias = (z==0)?b0:(z==1)?b1:b2;
    void* Cv           = (z==0)?O0:(z==1)?O1:O2;
    float oscale       = (QKV && z==0) ? qs : 1.f;

    int tid=threadIdx.x, lane=tid&31;
    int warp=tid>>5, wm=warp>>1, wn=warp&1;
    int bm=blockIdx.y*128, bn=blockIdx.x*128;

    const __half* Ab = A  + (size_t)bm * D_;
    const __half* Bb = Wt + (size_t)bn * D_;

    float acc[4][8][4];
#pragma unroll
    for(int i=0;i<4;i++)
#pragma unroll
      for(int j=0;j<8;j++)
#pragma unroll
        for(int r=0;r<4;r++) acc[i][j][r]=0.f;

    int prr = tid>>3, prc = tid&7;
    uint32_t stoff[8]; int prow[8];
#pragma unroll
    for(int it=0;it<8;it++){
        int r = prr + 16*it;
        prow[it] = r;
        stoff[it] = r*128 + 16*(prc ^ (r&7));
    }

    int l7=lane&7, g8=(lane>>3)&1, g16=lane>>4;
    uint32_t aRow[4]; int aSwz[4];
#pragma unroll
    for(int mt=0;mt<4;mt++){
        int r = wm*64 + mt*16 + l7 + g8*8;
        aRow[mt] = r*128; aSwz[mt] = r&7;
    }
    uint32_t bRow[4]; int bSwz[4];
#pragma unroll
    for(int ntp=0;ntp<4;ntp++){
        int n = wn*64 + ntp*16 + l7 + g16*8;
        bRow[ntp] = 16384u + n*128; bSwz[ntp] = n&7;
    }

    auto issue=[&](int ch){
        int s = ch % 3;
        uint32_t da = sb + s*GS;
#pragma unroll
        for(int it=0;it<8;it++){
            cp16(da + stoff[it],          Ab + (size_t)prow[it]*D_ + ch*64 + prc*8);
            cp16(da + 16384 + stoff[it],  Bb + (size_t)prow[it]*D_ + ch*64 + prc*8);
        }
        CP_COMMIT();
    };

    issue(0); issue(1);

    for(int ch=0; ch<16; ch++){
        if(ch<15) CP_WAIT1(); else CP_WAIT0();
        __syncthreads();
        if(ch+2<16) issue(ch+2);
        uint32_t so = sb + (ch%3)*GS;
#pragma unroll
        for(int ks=0;ks<4;ks++){
            unsigned bf[4][4];
#pragma unroll
            for(int ntp=0;ntp<4;ntp++)
                ldsm_x4(bf[ntp], so + bRow[ntp] + 16*((2*ks+g8)^bSwz[ntp]));
#pragma unroll
            for(int mt=0;mt<4;mt++){
                unsigned af[4];
                ldsm_x4(af, so + aRow[mt] + 16*((2*ks+g16)^aSwz[mt]));
#pragma unroll
                for(int ntp=0;ntp<4;ntp++){
                    mma16(acc[mt][2*ntp+0], af, &bf[ntp][0]);
                    mma16(acc[mt][2*ntp+1], af, &bf[ntp][2]);
                }
            }
        }
    }

#pragma unroll
    for(int mt=0;mt<4;mt++){
        int r0 = bm + wm*64 + mt*16 + (lane>>2);
#pragma unroll
        for(int hf=0;hf<2;hf++){
            int m = r0 + hf*8;
            int bidx = m>>11, l = m&(L_-1);
#pragma unroll
            for(int nt=0;nt<8;nt++){
                int n = bn + wn*64 + nt*8 + 2*(lane&3);
                float2 bb = *(const float2*)&bias[n];
                float v0 = (acc[mt][nt][hf*2+0] + bb.x) * oscale;
                float v1 = (acc[mt][nt][hf*2+1] + bb.y) * oscale;
                if(QKV){
                    int h=n>>6, dd=n&63;
                    *(half2*)&((__half*)Cv)[(size_t)((bidx*H_+h)*L_+l)*DH + dd] =
                        __floats2half2_rn(v0, v1);
                } else {
                    float2 ov = make_float2(v0, v1);
                    *(float2*)&((float*)Cv)[(size_t)m*D_ + n] = ov;
                }
            }
        }
    }
}

// -------------------- fp16 flash attention v8: key-split + rescale skip ----------
// 64-row Q tiles; 8 warps = 4 row-groups x 2 key-halves, independent (m,l,O) per
// half merged once at the end. o-rescale skipped (bit-identical) when the warp's
// corr factors are exactly 1.0.
#define AQ 0                 /* 8KB  (64 rows) */
#define AK 8192              /* 2 x 16KB */
#define AV 40960             /* 2 x 16KB */
#define APAD 73728           /* 128 floats */
#define AFLAG (APAD + 512)
#define ATTN_SMEM (AFLAG + 16)

__global__ void __launch_bounds__(256, 2)
attn_h(const unsigned char* __restrict__ pad, __half* __restrict__ outp){
    extern __shared__ __align__(128) char smem[];
    uint32_t sb = smem_u32(smem);
    float* spad = (float*)(smem + APAD);
    int* flagp  = (int*)(smem + AFLAG);

    int tid=threadIdx.x, lane=tid&31, warp=tid>>5;
    int rgrp = warp & 3, kh = warp >> 2;
    int qt = (int)(gridDim.x - 1) - (int)blockIdx.x;   // 0..31, long blocks first
    int bh=blockIdx.y;
    int b=bh>>4, h=bh&15;
    const __half* Q = g_Qh + (size_t)bh*L_*DH;
    const __half* K = g_Kh + (size_t)bh*L_*DH;
    const __half* V = g_Vh + (size_t)bh*L_*DH;

    // async load Q tile: 64 rows x 8 chunks (512 cp16)
#pragma unroll
    for(int t=0;t<2;t++){
        int idx=t*256+tid;
        int r=idx>>3, c=idx&7;
        cp16(sb + AQ + r*128 + 16*(c ^ (r&7)),
             Q + (size_t)(qt*64+r)*DH + c*8);
    }
    CP_COMMIT();

    auto issueKV=[&](int kt2){
        uint32_t buf = (kt2&1)*16384u;
#pragma unroll
        for(int t=0;t<4;t++){
            int idx=t*256+tid;
            int r=idx>>3, c=idx&7;
            uint32_t off = r*128 + 16*(c ^ (r&7));
            cp16(sb + AK + buf + off, K + (size_t)(kt2*128+r)*DH + c*8);
            cp16(sb + AV + buf + off, V + (size_t)(kt2*128+r)*DH + c*8);
        }
        CP_COMMIT();
    };
    issueKV(0);

    int row_min = qt*64;
    int nkt2 = (qt*64 + 63)/128 + 1;

    // block-level padding flag over the whole key range (once)
    if(tid==0) *flagp = 0;
    __syncthreads();
    {
        int npad = nkt2*128;
        unsigned a=0;
        for(int i=tid*4; i<npad; i+=1024)
            a |= *(const unsigned*)(pad + b*L_ + i);
        a = __reduce_or_sync(0xffffffffu, a);
        if((tid&31)==0 && a) atomicOr(flagp, 1);
    }
    __syncthreads();
    bool haspad = (*flagp) != 0;

    int l7=lane&7, g8=(lane>>3)&1, g16=lane>>4;
    int rqa = rgrp*16 + l7 + g8*8;
    uint32_t qOff = AQ + rqa*128;  int qSwz = rqa&7;
    uint32_t kBase = AK + (uint32_t)(kh*64 + l7 + g16*8)*128;
    int kSwzB = (l7 + g16*8) & 7;
    uint32_t vBase = AV + (uint32_t)(kh*64 + l7 + g8*8)*128;
    int vSwzB = (l7 + g8*8) & 7;
    int rq0 = lane>>2;

    const unsigned onesf[2] = {0x3C003C00u, 0x3C003C00u};

    float m_[2]={-1e30f,-1e30f}, l_[2]={0.f,0.f};
    float o[8][4];
#pragma unroll
    for(int i=0;i<8;i++){o[i][0]=0.f;o[i][1]=0.f;o[i][2]=0.f;o[i][3]=0.f;}
    int r0g = qt*64 + rgrp*16 + rq0;
    int r1g = r0g + 8;

    for(int kt2=0;kt2<nkt2;kt2++){
        __syncthreads();
        if(kt2+1<nkt2){ issueKV(kt2+1); CP_WAIT1(); }
        else          { CP_WAIT0(); }
        if(haspad && warp==1){
#pragma unroll
            for(int j=0;j<4;j++){
                int idx = lane*4 + j;
                spad[idx] = pad[b*L_ + kt2*128 + idx] ? NEG : 0.f;
            }
        }
        __syncthreads();
        uint32_t buf = (kt2&1)*16384u;
        int c0 = kt2*128 + kh*64;          // warp's key base
        if(c0 > row_min) continue;          // fully causally masked: contributes 0
        bool diag = (c0 == row_min);
        const float* sp = spad + kh*64;

        // ---- S = Q K^T over warp's 64 keys ----
        float s[8][4];
#pragma unroll
        for(int i=0;i<8;i++){s[i][0]=0.f;s[i][1]=0.f;s[i][2]=0.f;s[i][3]=0.f;}
#pragma unroll
        for(int ks=0;ks<4;ks++){
            unsigned af[4];
            ldsm_x4(af, sb + qOff + 16*((2*ks + g16) ^ qSwz));
#pragma unroll
            for(int ntp=0;ntp<4;ntp++){
                unsigned bf[4];
                ldsm_x4(bf, sb + kBase + buf + ntp*2048u + 16*((2*ks + g8) ^ kSwzB));
                mma16(s[2*ntp+0], af, &bf[0]);
                mma16(s[2*ntp+1], af, &bf[2]);
            }
        }

        // ---- mask + row max ----
        float rmax0=-1e30f, rmax1=-1e30f;
        if(diag){
            if(haspad){
#pragma unroll
                for(int nt=0;nt<8;nt++){
                    int cl = nt*8 + 2*(lane&3);
                    int cg0 = c0 + cl, cg1 = cg0+1;
                    float ms0=sp[cl], ms1=sp[cl+1];
                    float v0=s[nt][0] - ms0; if(cg0>r0g) v0-=NEG;
                    float v1=s[nt][1] - ms1; if(cg1>r0g) v1-=NEG;
                    float v2=s[nt][2] - ms0; if(cg0>r1g) v2-=NEG;
                    float v3=s[nt][3] - ms1; if(cg1>r1g) v3-=NEG;
                    s[nt][0]=v0; s[nt][1]=v1; s[nt][2]=v2; s[nt][3]=v3;
                    rmax0=fmaxf(rmax0,fmaxf(v0,v1));
                    rmax1=fmaxf(rmax1,fmaxf(v2,v3));
                }
            } else {
#pragma unroll
                for(int nt=0;nt<8;nt++){
                    int cl = nt*8 + 2*(lane&3);
                    int cg0 = c0 + cl, cg1 = cg0+1;
                    float v0=s[nt][0]; if(cg0>r0g) v0-=NEG;
                    float v1=s[nt][1]; if(cg1>r0g) v1-=NEG;
                    float v2=s[nt][2]; if(cg0>r1g) v2-=NEG;
                    float v3=s[nt][3]; if(cg1>r1g) v3-=NEG;
                    s[nt][0]=v0; s[nt][1]=v1; s[nt][2]=v2; s[nt][3]=v3;
                    rmax0=fmaxf(rmax0,fmaxf(v0,v1));
                    rmax1=fmaxf(rmax1,fmaxf(v2,v3));
                }
            }
        } else {
            if(haspad){
#pragma unroll
                for(int nt=0;nt<8;nt++){
                    int cl = nt*8 + 2*(lane&3);
                    float ms0=sp[cl], ms1=sp[cl+1];
                    float v0=s[nt][0] - ms0;
                    float v1=s[nt][1] - ms1;
                    float v2=s[nt][2] - ms0;
                    float v3=s[nt][3] - ms1;
                    s[nt][0]=v0; s[nt][1]=v1; s[nt][2]=v2; s[nt][3]=v3;
                    rmax0=fmaxf(rmax0,fmaxf(v0,v1));
                    rmax1=fmaxf(rmax1,fmaxf(v2,v3));
                }
            } else {
#pragma unroll
                for(int nt=0;nt<8;nt++){
                    rmax0=fmaxf(rmax0,fmaxf(s[nt][0],s[nt][1]));
                    rmax1=fmaxf(rmax1,fmaxf(s[nt][2],s[nt][3]));
                }
            }
        }

        // ---- packed half2 max reduce (2 shfl) ----
        rmax0 = fmaxf(rmax0, -60000.f);
        rmax1 = fmaxf(rmax1, -60000.f);
        half2 mh = __floats2half2_rn(rmax0, rmax1);
        unsigned mu = *(unsigned*)&mh;
        unsigned ms1_ = __shfl_xor_sync(0xffffffffu, mu, 1);
        mh = __hmax2(mh, *(half2*)&ms1_);
        mu = *(unsigned*)&mh;
        unsigned ms2_ = __shfl_xor_sync(0xffffffffu, mu, 2);
        mh = __hmax2(mh, *(half2*)&ms2_);
        float2 rmf = __half22float2(mh);

        float mn0=fmaxf(m_[0],rmf.x), mn1=fmaxf(m_[1],rmf.y);
        float corr0=fexp2(m_[0]-mn0), corr1=fexp2(m_[1]-mn1);
        m_[0]=mn0; m_[1]=mn1;

        // ---- exp2 in f16x2 -> P stays in registers ----
        unsigned eh01[8], eh23[8];
#pragma unroll
        for(int nt=0;nt<8;nt++){
            half2 e01 = h2exp2(__floats2half2_rn(s[nt][0]-mn0, s[nt][1]-mn0));
            half2 e23 = h2exp2(__floats2half2_rn(s[nt][2]-mn1, s[nt][3]-mn1));
            eh01[nt] = *(unsigned*)&e01;
            eh23[nt] = *(unsigned*)&e23;
        }
        // o-rescale: skip when corr==1 exactly (x*1.0f==x, bit-identical)
        if(!__all_sync(0xffffffffu, (corr0==1.f) && (corr1==1.f))){
#pragma unroll
            for(int nt=0;nt<8;nt++){
                o[nt][0]*=corr0; o[nt][1]*=corr0;
                o[nt][2]*=corr1; o[nt][3]*=corr1;
            }
            l_[0]*=corr0; l_[1]*=corr1;
        }

        // ---- O += P V ; row sums via P*ones MMA ----
        float lsum[4]={0.f,0.f,0.f,0.f};
#pragma unroll
        for(int ks=0;ks<4;ks++){
            unsigned pf[4] = {eh01[2*ks], eh23[2*ks], eh01[2*ks+1], eh23[2*ks+1]};
            mma16(lsum, pf, onesf);
            uint32_t vb = vBase + buf + ks*2048u;
#pragma unroll
            for(int ntp=0;ntp<4;ntp++){
                unsigned bf[4];
                ldsm_x4t(bf, sb + vb + 16*((2*ntp + g16) ^ vSwzB));
                mma16(o[2*ntp+0], pf, &bf[0]);
                mma16(o[2*ntp+1], pf, &bf[2]);
            }
        }
        l_[0]+=lsum[0];
        l_[1]+=lsum[2];
    }

    // ---- cross-half merge: kh=1 stages (m,l,O) in smem; kh=0 combines ----
    __syncthreads();                       // KV buffers dead; reuse as staging
    if(kh==1){
#pragma unroll
        for(int nt=0;nt<8;nt++){
            float4 v = make_float4(o[nt][0], o[nt][1], o[nt][2], o[nt][3]);
            *(float4*)(smem + AK + rgrp*4096 + lane*128 + 16*(nt ^ (lane&7))) = v;
        }
        *(float4*)(smem + AV + rgrp*512 + lane*16) =
            make_float4(m_[0], m_[1], l_[0], l_[1]);
    }
    __syncthreads();
    if(kh==0){
        float4 ml = *(const float4*)(smem + AV + rgrp*512 + lane*16);
        float M0 = fmaxf(m_[0], ml.x), M1 = fmaxf(m_[1], ml.y);
        float ca0 = fexp2(m_[0]-M0), cb0 = fexp2(ml.x-M0);
        float ca1 = fexp2(m_[1]-M1), cb1 = fexp2(ml.y-M1);
        float L0 = l_[0]*ca0 + ml.z*cb0;
        float L1 = l_[1]*ca1 + ml.w*cb1;
        float inv0 = 1.f/L0, inv1 = 1.f/L1;
#pragma unroll
        for(int nt=0;nt<8;nt++){
            float4 ov = *(const float4*)(smem + AK + rgrp*4096 + lane*128 + 16*(nt ^ (lane&7)));
            float r0 = (o[nt][0]*ca0 + ov.x*cb0) * inv0;
            float r1 = (o[nt][1]*ca0 + ov.y*cb0) * inv0;
            float r2 = (o[nt][2]*ca1 + ov.z*cb1) * inv1;
            float r3 = (o[nt][3]*ca1 + ov.w*cb1) * inv1;
            int dd = nt*8 + 2*(lane&3);
            *(half2*)&outp[(size_t)(b*L_+r0g)*D_ + h*DH + dd] = __floats2half2_rn(r0, r1);
            *(half2*)&outp[(size_t)(b*L_+r1g)*D_ + h*DH + dd] = __floats2half2_rn(r2, r3);
        }
    }
}

// -------------------- launch --------------------
extern "C" void kernel_launch(void* const* d_in, const int* in_sizes, int n_in,
                              void* d_out, int out_size) {
    const float* q  = (const float*)d_in[0];
    const float* k  = (const float*)d_in[1];
    const float* v  = (const float*)d_in[2];
    const unsigned char* pad = (const unsigned char*)d_in[3];
    const float* Wq = (const float*)d_in[4];
    const float* bq = (const float*)d_in[5];
    const float* Wk = (const float*)d_in[6];
    const float* bk = (const float*)d_in[7];
    const float* Wv = (const float*)d_in[8];
    const float* bv = (const float*)d_in[9];
    const float* Wo = (const float*)d_in[10];
    const float* bo = (const float*)d_in[11];
    float* out = (float*)d_out;

    __half *p_qpe, *p_kpe, *p_vr, *p_Qh, *p_Kh, *p_Vh, *p_attn, *p_Wt;
    cudaGetSymbolAddress((void**)&p_qpe,  g_qpe);
    cudaGetSymbolAddress((void**)&p_kpe,  g_kpe);
    cudaGetSymbolAddress((void**)&p_vr,   g_vr);
    cudaGetSymbolAddress((void**)&p_Qh,   g_Qh);
    cudaGetSymbolAddress((void**)&p_Kh,   g_Kh);
    cudaGetSymbolAddress((void**)&p_Vh,   g_Vh);
    cudaGetSymbolAddress((void**)&p_attn, g_attn);
    cudaGetSymbolAddress((void**)&p_Wt,   g_Wt);

    cudaFuncSetAttribute(attn_h, cudaFuncAttributeMaxDynamicSharedMemorySize, ATTN_SMEM);
    cudaFuncSetAttribute(gemm_h5<0>, cudaFuncAttributeMaxDynamicSharedMemorySize, G_SMEM);
    cudaFuncSetAttribute(gemm_h5<1>, cudaFuncAttributeMaxDynamicSharedMemorySize, G_SMEM);

    // 0) weight transposes -> half [N][K]
    transpose_w4<<<dim3(32,32,4), dim3(32,8)>>>(Wq, Wk, Wv, Wo);

    // 1) positional encodings -> half
    int pe_threads = M_ * NF_;
    pe_add_kernel<<<(pe_threads + 255) / 256, 256>>>(q, k, v);

    // 2) fused QKV projections -> head layout (half); Q pre-scaled by 0.125*log2e
    gemm_h5<1><<<dim3(8, 64, 3), 128, G_SMEM>>>(
        p_qpe, p_kpe, p_vr, p_Wt, bq, bk, bv,
        (void*)p_Qh, (void*)p_Kh, (void*)p_Vh, 0.18033688f);

    // 3) fused causal flash attention (key-split + rescale skip)
    attn_h<<<dim3(L_ / 64, B_ * H_), 256, ATTN_SMEM>>>(pad, p_attn);

    // 4) output projection -> fp32 d_out
    gemm_h5<0><<<dim3(8, 64, 1), 128, G_SMEM>>>(
        p_attn, nullptr, nullptr, p_Wt, bo, nullptr, nullptr,
        (void*)out, nullptr, nullptr, 1.0f);
}